// round 1
// baseline (speedup 1.0000x reference)
#include <cuda_runtime.h>
#include <math.h>

#define Bc  2
#define Sc  4096
#define DMc 512
#define Hc  8
#define Dc  64
#define Mc  (Bc * Sc)   // 8192

// Scratch: projected Q/K/V in [B*H, S, D] layout, attention output in [B, S, DM].
__device__ float g_Qp[Bc * Hc * Sc * Dc];
__device__ float g_Kp[Bc * Hc * Sc * Dc];
__device__ float g_Vp[Bc * Hc * Sc * Dc];
__device__ float g_Ao[Bc * Sc * DMc];

// ---------------------------------------------------------------------------
// GEMM: C[M=8192, N=512] = X[M,512] @ W[512,512] + bias
// 128x128 block tile, BK=16, 256 threads, 8x8 per-thread register tile.
// SPLIT=true writes head-split layout [(b*H+h)*S + s]*64 + d, else row-major.
// ---------------------------------------------------------------------------
template <bool SPLIT>
__global__ __launch_bounds__(256, 2)
void gemm512(const float* __restrict__ X, const float* __restrict__ W,
             const float* __restrict__ bias, float* __restrict__ out)
{
    __shared__ float As[16][132];   // A transposed: As[k][m]
    __shared__ float Bs[16][132];   // Bs[k][n]

    const int tid = threadIdx.x;
    const int tx  = tid & 15;
    const int ty  = tid >> 4;
    const int m0  = blockIdx.y << 7;
    const int n0  = blockIdx.x << 7;

    float acc[8][8];
#pragma unroll
    for (int i = 0; i < 8; i++)
#pragma unroll
        for (int j = 0; j < 8; j++) acc[i][j] = 0.f;

    for (int k0 = 0; k0 < DMc; k0 += 16) {
        // Load A tile 128x16 (transposed into smem)
#pragma unroll
        for (int p = 0; p < 2; p++) {
            int f  = tid + (p << 8);
            int r  = f >> 2;            // 0..127
            int c4 = (f & 3) << 2;      // 0,4,8,12
            float4 v = *(const float4*)(X + (m0 + r) * DMc + k0 + c4);
            As[c4 + 0][r] = v.x;
            As[c4 + 1][r] = v.y;
            As[c4 + 2][r] = v.z;
            As[c4 + 3][r] = v.w;
        }
        // Load B tile 16x128
#pragma unroll
        for (int p = 0; p < 2; p++) {
            int f  = tid + (p << 8);
            int kr = f >> 5;            // 0..15
            int n4 = (f & 31) << 2;     // 0..124
            *(float4*)&Bs[kr][n4] =
                *(const float4*)(W + (k0 + kr) * DMc + n0 + n4);
        }
        __syncthreads();

#pragma unroll
        for (int kk = 0; kk < 16; kk++) {
            float a[8], b[8];
            *(float4*)(a)     = *(const float4*)&As[kk][ty * 8];
            *(float4*)(a + 4) = *(const float4*)&As[kk][ty * 8 + 4];
            *(float4*)(b)     = *(const float4*)&Bs[kk][tx * 8];
            *(float4*)(b + 4) = *(const float4*)&Bs[kk][tx * 8 + 4];
#pragma unroll
            for (int i = 0; i < 8; i++)
#pragma unroll
                for (int j = 0; j < 8; j++)
                    acc[i][j] += a[i] * b[j];
        }
        __syncthreads();
    }

    // Epilogue
#pragma unroll
    for (int i = 0; i < 8; i++) {
        int m  = m0 + ty * 8 + i;
        int b_ = m >> 12;           // m / 4096
        int s_ = m & (Sc - 1);
#pragma unroll
        for (int j4 = 0; j4 < 8; j4 += 4) {
            int n = n0 + tx * 8 + j4;
            float4 v;
            v.x = acc[i][j4 + 0] + bias[n + 0];
            v.y = acc[i][j4 + 1] + bias[n + 1];
            v.z = acc[i][j4 + 2] + bias[n + 2];
            v.w = acc[i][j4 + 3] + bias[n + 3];
            if (SPLIT) {
                int h = n >> 6;
                int d = n & 63;
                *(float4*)(out + ((b_ * Hc + h) * Sc + s_) * Dc + d) = v;
            } else {
                *(float4*)(out + m * DMc + n) = v;
            }
        }
    }
}

// ---------------------------------------------------------------------------
// Flash attention (fp32): per block = one (b,h) x 64 query rows, loop over
// 64-wide K tiles with online softmax. Q pre-scaled by 1/sqrt(D)=0.125.
// Dynamic smem: Qs[d][q], Ks[d][k], Vs[k][d], Ps[q][k] (all 64x68), mask[64].
// ---------------------------------------------------------------------------
#define ATTN_SMEM_FLOATS (4 * 64 * 68 + 64)
#define ATTN_SMEM_BYTES  (ATTN_SMEM_FLOATS * 4)

__global__ __launch_bounds__(256, 2)
void attn64(const float* __restrict__ Qp, const float* __restrict__ Kp,
            const float* __restrict__ Vp, const float* __restrict__ mask,
            float* __restrict__ Ao)
{
    extern __shared__ float sm[];
    float (*Qs)[68] = (float(*)[68])(sm);
    float (*Ks)[68] = (float(*)[68])(sm + 64 * 68);
    float (*Vs)[68] = (float(*)[68])(sm + 2 * 64 * 68);
    float (*Ps)[68] = (float(*)[68])(sm + 3 * 64 * 68);
    float* mk = sm + 4 * 64 * 68;

    const int tid = threadIdx.x;
    const int tx  = tid & 15;     // 4 key-cols / d-cols
    const int ty  = tid >> 4;     // 4 query-rows
    const int bh  = blockIdx.y;   // b*H + h
    const int b   = bh >> 3;
    const int q0  = blockIdx.x << 6;

    const float* Qb = Qp + ((size_t)bh * Sc + q0) * Dc;
    const float* Kb = Kp + (size_t)bh * Sc * Dc;
    const float* Vb = Vp + (size_t)bh * Sc * Dc;

    // Load Q tile, transposed, pre-scaled
#pragma unroll
    for (int p = 0; p < 4; p++) {
        int qr = ty + (p << 4);
        float4 v = *(const float4*)(Qb + qr * Dc + tx * 4);
        Qs[tx * 4 + 0][qr] = v.x * 0.125f;
        Qs[tx * 4 + 1][qr] = v.y * 0.125f;
        Qs[tx * 4 + 2][qr] = v.z * 0.125f;
        Qs[tx * 4 + 3][qr] = v.w * 0.125f;
    }

    float m_i[4], l_i[4], o[4][4];
#pragma unroll
    for (int i = 0; i < 4; i++) {
        m_i[i] = -INFINITY;
        l_i[i] = 0.f;
#pragma unroll
        for (int j = 0; j < 4; j++) o[i][j] = 0.f;
    }

    for (int k0 = 0; k0 < Sc; k0 += 64) {
        // Load K (transposed) and V (direct), plus mask slice
#pragma unroll
        for (int p = 0; p < 4; p++) {
            int kr = ty + (p << 4);
            const float* kp = Kb + (size_t)(k0 + kr) * Dc + tx * 4;
            const float* vp = Vb + (size_t)(k0 + kr) * Dc + tx * 4;
            float4 kv = *(const float4*)kp;
            Ks[tx * 4 + 0][kr] = kv.x;
            Ks[tx * 4 + 1][kr] = kv.y;
            Ks[tx * 4 + 2][kr] = kv.z;
            Ks[tx * 4 + 3][kr] = kv.w;
            *(float4*)&Vs[kr][tx * 4] = *(const float4*)vp;
        }
        if (tid < 64) mk[tid] = mask[b * Sc + k0 + tid] * (-1e9f);
        __syncthreads();

        // S = (Q*scale) @ K^T
        float s[4][4];
#pragma unroll
        for (int i = 0; i < 4; i++)
#pragma unroll
            for (int j = 0; j < 4; j++) s[i][j] = 0.f;

#pragma unroll 8
        for (int d = 0; d < 64; d++) {
            float4 a  = *(const float4*)&Qs[d][ty * 4];
            float4 bb = *(const float4*)&Ks[d][tx * 4];
            float av[4] = {a.x, a.y, a.z, a.w};
            float bv[4] = {bb.x, bb.y, bb.z, bb.w};
#pragma unroll
            for (int i = 0; i < 4; i++)
#pragma unroll
                for (int j = 0; j < 4; j++)
                    s[i][j] += av[i] * bv[j];
        }

        // Mask + online softmax (row groups = 16 threads sharing ty)
        float4 mv = *(const float4*)&mk[tx * 4];
        float mvv[4] = {mv.x, mv.y, mv.z, mv.w};
#pragma unroll
        for (int i = 0; i < 4; i++) {
            float rmax = -INFINITY;
#pragma unroll
            for (int j = 0; j < 4; j++) {
                s[i][j] += mvv[j];
                rmax = fmaxf(rmax, s[i][j]);
            }
#pragma unroll
            for (int ofs = 8; ofs > 0; ofs >>= 1)
                rmax = fmaxf(rmax, __shfl_xor_sync(0xffffffffu, rmax, ofs));
            float mn    = fmaxf(m_i[i], rmax);
            float alpha = __expf(m_i[i] - mn);
            m_i[i] = mn;
            float rsum = 0.f;
#pragma unroll
            for (int j = 0; j < 4; j++) {
                float pv = __expf(s[i][j] - mn);
                s[i][j] = pv;
                rsum += pv;
            }
#pragma unroll
            for (int ofs = 8; ofs > 0; ofs >>= 1)
                rsum += __shfl_xor_sync(0xffffffffu, rsum, ofs);
            l_i[i] = l_i[i] * alpha + rsum;
#pragma unroll
            for (int j = 0; j < 4; j++) o[i][j] *= alpha;
        }

        // Stage P to smem for the PV matmul
#pragma unroll
        for (int i = 0; i < 4; i++)
            *(float4*)&Ps[ty * 4 + i][tx * 4] =
                make_float4(s[i][0], s[i][1], s[i][2], s[i][3]);
        __syncthreads();

        // O += P @ V
#pragma unroll 8
        for (int k = 0; k < 64; k++) {
            float av[4];
            av[0] = Ps[ty * 4 + 0][k];
            av[1] = Ps[ty * 4 + 1][k];
            av[2] = Ps[ty * 4 + 2][k];
            av[3] = Ps[ty * 4 + 3][k];
            float4 bb = *(const float4*)&Vs[k][tx * 4];
            float bv[4] = {bb.x, bb.y, bb.z, bb.w};
#pragma unroll
            for (int i = 0; i < 4; i++)
#pragma unroll
                for (int j = 0; j < 4; j++)
                    o[i][j] += av[i] * bv[j];
        }
        __syncthreads();
    }

    // Normalize + write to [B, S, DM] layout (heads re-interleaved)
#pragma unroll
    for (int i = 0; i < 4; i++) {
        float inv = 1.f / l_i[i];
        int qr = q0 + ty * 4 + i;
        float4 v = make_float4(o[i][0] * inv, o[i][1] * inv,
                               o[i][2] * inv, o[i][3] * inv);
        *(float4*)(Ao + ((size_t)b * Sc + qr) * DMc + (bh & 7) * Dc + tx * 4) = v;
    }
}

// ---------------------------------------------------------------------------
extern "C" void kernel_launch(void* const* d_in, const int* in_sizes, int n_in,
                              void* d_out, int out_size)
{
    const float* q    = (const float*)d_in[0];
    const float* k    = (const float*)d_in[1];
    const float* v    = (const float*)d_in[2];
    const float* mask = (const float*)d_in[3];
    const float* Wq   = (const float*)d_in[4];
    const float* bq   = (const float*)d_in[5];
    const float* Wk   = (const float*)d_in[6];
    const float* bk   = (const float*)d_in[7];
    const float* Wv   = (const float*)d_in[8];
    const float* bv   = (const float*)d_in[9];
    const float* Wo   = (const float*)d_in[10];
    const float* bo   = (const float*)d_in[11];
    float* out = (float*)d_out;

    float *Qp, *Kp, *Vp, *Ao;
    cudaGetSymbolAddress((void**)&Qp, g_Qp);
    cudaGetSymbolAddress((void**)&Kp, g_Kp);
    cudaGetSymbolAddress((void**)&Vp, g_Vp);
    cudaGetSymbolAddress((void**)&Ao, g_Ao);

    cudaFuncSetAttribute(attn64, cudaFuncAttributeMaxDynamicSharedMemorySize,
                         ATTN_SMEM_BYTES);

    dim3 gg(DMc / 128, Mc / 128);   // (4, 64)
    gemm512<true><<<gg, 256>>>(q, Wq, bq, Qp);
    gemm512<true><<<gg, 256>>>(k, Wk, bk, Kp);
    gemm512<true><<<gg, 256>>>(v, Wv, bv, Vp);

    dim3 ga(Sc / 64, Bc * Hc);      // (64, 16)
    attn64<<<ga, 256, ATTN_SMEM_BYTES>>>(Qp, Kp, Vp, mask, Ao);

    gemm512<false><<<gg, 256>>>(Ao, Wo, bo, out);
}

// round 2
// speedup vs baseline: 1.7650x; 1.7650x over previous
#include <cuda_runtime.h>
#include <math.h>

#define Bc  2
#define Sc  4096
#define DMc 512
#define Hc  8
#define Dc  64
#define Mc  (Bc * Sc)   // 8192

// Scratch: projected Q/K/V in [B*H, S, D] layout, attention output in [B, S, DM].
__device__ float g_Qp[Bc * Hc * Sc * Dc];
__device__ float g_Kp[Bc * Hc * Sc * Dc];
__device__ float g_Vp[Bc * Hc * Sc * Dc];
__device__ float g_Ao[Bc * Sc * DMc];

// ---------------------------------------------------------------------------
// GEMM: C[M=8192, N=512] = X[M,512] @ W[512,512] + bias (fp32 FFMA)
// ---------------------------------------------------------------------------
template <bool SPLIT>
__global__ __launch_bounds__(256, 2)
void gemm512(const float* __restrict__ X, const float* __restrict__ W,
             const float* __restrict__ bias, float* __restrict__ out)
{
    __shared__ float As[16][132];
    __shared__ float Bs[16][132];

    const int tid = threadIdx.x;
    const int tx  = tid & 15;
    const int ty  = tid >> 4;
    const int m0  = blockIdx.y << 7;
    const int n0  = blockIdx.x << 7;

    float acc[8][8];
#pragma unroll
    for (int i = 0; i < 8; i++)
#pragma unroll
        for (int j = 0; j < 8; j++) acc[i][j] = 0.f;

    for (int k0 = 0; k0 < DMc; k0 += 16) {
#pragma unroll
        for (int p = 0; p < 2; p++) {
            int f  = tid + (p << 8);
            int r  = f >> 2;
            int c4 = (f & 3) << 2;
            float4 v = *(const float4*)(X + (m0 + r) * DMc + k0 + c4);
            As[c4 + 0][r] = v.x;
            As[c4 + 1][r] = v.y;
            As[c4 + 2][r] = v.z;
            As[c4 + 3][r] = v.w;
        }
#pragma unroll
        for (int p = 0; p < 2; p++) {
            int f  = tid + (p << 8);
            int kr = f >> 5;
            int n4 = (f & 31) << 2;
            *(float4*)&Bs[kr][n4] =
                *(const float4*)(W + (k0 + kr) * DMc + n0 + n4);
        }
        __syncthreads();

#pragma unroll
        for (int kk = 0; kk < 16; kk++) {
            float a[8], b[8];
            *(float4*)(a)     = *(const float4*)&As[kk][ty * 8];
            *(float4*)(a + 4) = *(const float4*)&As[kk][ty * 8 + 4];
            *(float4*)(b)     = *(const float4*)&Bs[kk][tx * 8];
            *(float4*)(b + 4) = *(const float4*)&Bs[kk][tx * 8 + 4];
#pragma unroll
            for (int i = 0; i < 8; i++)
#pragma unroll
                for (int j = 0; j < 8; j++)
                    acc[i][j] += a[i] * b[j];
        }
        __syncthreads();
    }

#pragma unroll
    for (int i = 0; i < 8; i++) {
        int m  = m0 + ty * 8 + i;
        int b_ = m >> 12;
        int s_ = m & (Sc - 1);
#pragma unroll
        for (int j4 = 0; j4 < 8; j4 += 4) {
            int n = n0 + tx * 8 + j4;
            float4 v;
            v.x = acc[i][j4 + 0] + bias[n + 0];
            v.y = acc[i][j4 + 1] + bias[n + 1];
            v.z = acc[i][j4 + 2] + bias[n + 2];
            v.w = acc[i][j4 + 3] + bias[n + 3];
            if (SPLIT) {
                int h = n >> 6;
                int d = n & 63;
                *(float4*)(out + ((b_ * Hc + h) * Sc + s_) * Dc + d) = v;
            } else {
                *(float4*)(out + m * DMc + n) = v;
            }
        }
    }
}

// ---------------------------------------------------------------------------
// Flash attention with tf32 mma.sync (m16n8k8).
// Block: 256 threads (8 warps), BQ=128 query rows, BK=64 key tiles, D=64.
// Warp w owns query rows [16w, 16w+16), full N.
// smem (stride 68 -> conflict-free fragment LDS: bank = 4*group + tig):
//   Qs[128][68] tf32 bits (pre-scaled by 0.125)
//   Ks[64][68]  tf32 bits, [key][d]   (B operand of QK^T, col-major as n=key)
//   Vt[64][68]  tf32 bits, [d][key]   (B operand of PV,  col-major as n=d)
//   Ss[128][68] fp32 S, overwritten with tf32 P
//   mk[64], m_s/l_s/al_s[128]
// ---------------------------------------------------------------------------
#define QS_OFF 0
#define KS_OFF (128 * 68)
#define VT_OFF (KS_OFF + 64 * 68)
#define SS_OFF (VT_OFF + 64 * 68)
#define MK_OFF (SS_OFF + 128 * 68)
#define MS_OFF (MK_OFF + 64)
#define LS_OFF (MS_OFF + 128)
#define AL_OFF (LS_OFF + 128)
#define ATTN_SMEM_FLOATS (AL_OFF + 128)
#define ATTN_SMEM_BYTES  (ATTN_SMEM_FLOATS * 4)

__device__ __forceinline__ unsigned f2tf32(float x) {
    unsigned r;
    asm("cvt.rna.tf32.f32 %0, %1;" : "=r"(r) : "f"(x));
    return r;
}

__device__ __forceinline__ void mma_tf32(float c[4], unsigned a0, unsigned a1,
                                         unsigned a2, unsigned a3,
                                         unsigned b0, unsigned b1) {
    asm volatile(
        "mma.sync.aligned.m16n8k8.row.col.f32.tf32.tf32.f32 "
        "{%0,%1,%2,%3}, {%4,%5,%6,%7}, {%8,%9}, {%0,%1,%2,%3};\n"
        : "+f"(c[0]), "+f"(c[1]), "+f"(c[2]), "+f"(c[3])
        : "r"(a0), "r"(a1), "r"(a2), "r"(a3), "r"(b0), "r"(b1));
}

__global__ __launch_bounds__(256, 2)
void attn_mma(const float* __restrict__ Qp, const float* __restrict__ Kp,
              const float* __restrict__ Vp, const float* __restrict__ mask,
              float* __restrict__ Ao)
{
    extern __shared__ float sm[];
    unsigned* Qs = (unsigned*)(sm + QS_OFF);
    unsigned* Ks = (unsigned*)(sm + KS_OFF);
    unsigned* Vt = (unsigned*)(sm + VT_OFF);
    float*    Ss = sm + SS_OFF;
    unsigned* Su = (unsigned*)Ss;
    float*    mk = sm + MK_OFF;
    float*    m_s = sm + MS_OFF;
    float*    l_s = sm + LS_OFF;
    float*    al_s = sm + AL_OFF;

    const int tid  = threadIdx.x;
    const int wid  = tid >> 5;
    const int lane = tid & 31;
    const int g    = lane >> 2;      // groupID
    const int tig  = lane & 3;       // thread in group
    const int wm   = wid << 4;       // warp's 16-row base

    const int bh = blockIdx.y;
    const int b  = bh >> 3;
    const int h  = bh & 7;
    const int q0 = blockIdx.x << 7;

    const float* Qb = Qp + ((size_t)bh * Sc + q0) * Dc;
    const float* Kb = Kp + (size_t)bh * Sc * Dc;
    const float* Vb = Vp + (size_t)bh * Sc * Dc;

    // Load + scale + convert Q tile (128x64)
#pragma unroll
    for (int p = 0; p < 8; p++) {
        int idx = tid + (p << 8);          // 0..2047 float4 slots
        int r   = idx >> 4;
        int c4  = (idx & 15) << 2;
        float4 v = *(const float4*)(Qb + r * Dc + c4);
        Qs[r * 68 + c4 + 0] = f2tf32(v.x * 0.125f);
        Qs[r * 68 + c4 + 1] = f2tf32(v.y * 0.125f);
        Qs[r * 68 + c4 + 2] = f2tf32(v.z * 0.125f);
        Qs[r * 68 + c4 + 3] = f2tf32(v.w * 0.125f);
    }
    if (tid < 128) { m_s[tid] = -INFINITY; l_s[tid] = 0.f; }

    float o[8][4];
#pragma unroll
    for (int nt = 0; nt < 8; nt++)
#pragma unroll
        for (int j = 0; j < 4; j++) o[nt][j] = 0.f;

    for (int k0 = 0; k0 < Sc; k0 += 64) {
        // ---- load K (as [key][d]) and V (transposed [d][key]) tiles ----
#pragma unroll
        for (int p = 0; p < 4; p++) {
            int idx = tid + (p << 8);      // 0..1023 float4 slots
            int r   = idx >> 4;            // key row 0..63
            int c4  = (idx & 15) << 2;     // d 0..60
            float4 kv = *(const float4*)(Kb + (size_t)(k0 + r) * Dc + c4);
            float4 vv = *(const float4*)(Vb + (size_t)(k0 + r) * Dc + c4);
            Ks[r * 68 + c4 + 0] = f2tf32(kv.x);
            Ks[r * 68 + c4 + 1] = f2tf32(kv.y);
            Ks[r * 68 + c4 + 2] = f2tf32(kv.z);
            Ks[r * 68 + c4 + 3] = f2tf32(kv.w);
            Vt[(c4 + 0) * 68 + r] = f2tf32(vv.x);
            Vt[(c4 + 1) * 68 + r] = f2tf32(vv.y);
            Vt[(c4 + 2) * 68 + r] = f2tf32(vv.z);
            Vt[(c4 + 3) * 68 + r] = f2tf32(vv.w);
        }
        if (tid < 64) mk[tid] = mask[b * Sc + k0 + tid] * (-1e9f);
        __syncthreads();

        // ---- S = Q @ K^T via mma, store to Ss ----
        {
            float c[8][4];
#pragma unroll
            for (int nt = 0; nt < 8; nt++)
#pragma unroll
                for (int j = 0; j < 4; j++) c[nt][j] = 0.f;

#pragma unroll
            for (int kk = 0; kk < 8; kk++) {
                int kb = kk * 8 + tig;
                unsigned a0 = Qs[(wm + g) * 68 + kb];
                unsigned a1 = Qs[(wm + g + 8) * 68 + kb];
                unsigned a2 = Qs[(wm + g) * 68 + kb + 4];
                unsigned a3 = Qs[(wm + g + 8) * 68 + kb + 4];
#pragma unroll
                for (int nt = 0; nt < 8; nt++) {
                    unsigned b0 = Ks[(nt * 8 + g) * 68 + kb];
                    unsigned b1 = Ks[(nt * 8 + g) * 68 + kb + 4];
                    mma_tf32(c[nt], a0, a1, a2, a3, b0, b1);
                }
            }
#pragma unroll
            for (int nt = 0; nt < 8; nt++) {
                int col = nt * 8 + 2 * tig;
                *(float2*)&Ss[(wm + g) * 68 + col]     = make_float2(c[nt][0], c[nt][1]);
                *(float2*)&Ss[(wm + g + 8) * 68 + col] = make_float2(c[nt][2], c[nt][3]);
            }
        }
        __syncthreads();

        // ---- online softmax: thread pair (tid>>1) handles one row ----
        {
            int r  = tid >> 1;
            int hf = tid & 1;
            float* Srow = Ss + r * 68 + hf * 32;
            float* mkh  = mk + hf * 32;
            float sv[32];
            float vmax = -INFINITY;
#pragma unroll
            for (int j4 = 0; j4 < 32; j4 += 4) {
                float4 v = *(const float4*)(Srow + j4);
                float4 mv = *(const float4*)(mkh + j4);
                sv[j4 + 0] = v.x + mv.x;
                sv[j4 + 1] = v.y + mv.y;
                sv[j4 + 2] = v.z + mv.z;
                sv[j4 + 3] = v.w + mv.w;
#pragma unroll
                for (int j = 0; j < 4; j++) vmax = fmaxf(vmax, sv[j4 + j]);
            }
            vmax = fmaxf(vmax, __shfl_xor_sync(0xffffffffu, vmax, 1));
            float mold = m_s[r];
            float mn   = fmaxf(mold, vmax);
            float rsum = 0.f;
            unsigned* Purow = Su + r * 68 + hf * 32;
#pragma unroll
            for (int j = 0; j < 32; j++) {
                float pv = __expf(sv[j] - mn);
                rsum += pv;
                Purow[j] = f2tf32(pv);
            }
            rsum += __shfl_xor_sync(0xffffffffu, rsum, 1);
            if (hf == 0) {
                float alpha = __expf(mold - mn);
                m_s[r]  = mn;
                l_s[r]  = l_s[r] * alpha + rsum;
                al_s[r] = alpha;
            }
        }
        __syncthreads();

        // ---- O = O*alpha + P @ V via mma ----
        {
            float alpha0 = al_s[wm + g];
            float alpha1 = al_s[wm + g + 8];
#pragma unroll
            for (int nt = 0; nt < 8; nt++) {
                o[nt][0] *= alpha0; o[nt][1] *= alpha0;
                o[nt][2] *= alpha1; o[nt][3] *= alpha1;
            }
#pragma unroll
            for (int kk = 0; kk < 8; kk++) {
                int kb = kk * 8 + tig;
                unsigned a0 = Su[(wm + g) * 68 + kb];
                unsigned a1 = Su[(wm + g + 8) * 68 + kb];
                unsigned a2 = Su[(wm + g) * 68 + kb + 4];
                unsigned a3 = Su[(wm + g + 8) * 68 + kb + 4];
#pragma unroll
                for (int nt = 0; nt < 8; nt++) {
                    unsigned b0 = Vt[(nt * 8 + g) * 68 + kb];
                    unsigned b1 = Vt[(nt * 8 + g) * 68 + kb + 4];
                    mma_tf32(o[nt], a0, a1, a2, a3, b0, b1);
                }
            }
        }
        __syncthreads();
    }

    // ---- epilogue: normalize and write [B, S, DM] ----
    {
        float inv0 = 1.f / l_s[wm + g];
        float inv1 = 1.f / l_s[wm + g + 8];
        int row0 = q0 + wm + g;
#pragma unroll
        for (int nt = 0; nt < 8; nt++) {
            int d = nt * 8 + 2 * tig;
            *(float2*)(Ao + ((size_t)b * Sc + row0) * DMc + h * Dc + d) =
                make_float2(o[nt][0] * inv0, o[nt][1] * inv0);
            *(float2*)(Ao + ((size_t)b * Sc + row0 + 8) * DMc + h * Dc + d) =
                make_float2(o[nt][2] * inv1, o[nt][3] * inv1);
        }
    }
}

// ---------------------------------------------------------------------------
extern "C" void kernel_launch(void* const* d_in, const int* in_sizes, int n_in,
                              void* d_out, int out_size)
{
    const float* q    = (const float*)d_in[0];
    const float* k    = (const float*)d_in[1];
    const float* v    = (const float*)d_in[2];
    const float* mask = (const float*)d_in[3];
    const float* Wq   = (const float*)d_in[4];
    const float* bq   = (const float*)d_in[5];
    const float* Wk   = (const float*)d_in[6];
    const float* bk   = (const float*)d_in[7];
    const float* Wv   = (const float*)d_in[8];
    const float* bv   = (const float*)d_in[9];
    const float* Wo   = (const float*)d_in[10];
    const float* bo   = (const float*)d_in[11];
    float* out = (float*)d_out;

    float *Qp, *Kp, *Vp, *Ao;
    cudaGetSymbolAddress((void**)&Qp, g_Qp);
    cudaGetSymbolAddress((void**)&Kp, g_Kp);
    cudaGetSymbolAddress((void**)&Vp, g_Vp);
    cudaGetSymbolAddress((void**)&Ao, g_Ao);

    cudaFuncSetAttribute(attn_mma, cudaFuncAttributeMaxDynamicSharedMemorySize,
                         ATTN_SMEM_BYTES);

    dim3 gg(DMc / 128, Mc / 128);   // (4, 64)
    gemm512<true><<<gg, 256>>>(q, Wq, bq, Qp);
    gemm512<true><<<gg, 256>>>(k, Wk, bk, Kp);
    gemm512<true><<<gg, 256>>>(v, Wv, bv, Vp);

    dim3 ga(Sc / 128, Bc * Hc);     // (32, 16)
    attn_mma<<<ga, 256, ATTN_SMEM_BYTES>>>(Qp, Kp, Vp, mask, Ao);

    gemm512<false><<<gg, 256>>>(Ao, Wo, bo, out);
}

// round 3
// speedup vs baseline: 2.5003x; 1.4166x over previous
#include <cuda_runtime.h>
#include <math.h>

#define Bc  2
#define Sc  4096
#define DMc 512
#define Hc  8
#define Dc  64
#define Mc  (Bc * Sc)   // 8192

// Scratch: projected Q/K/V in [B*H, S, D] layout, attention output in [B, S, DM].
__device__ float g_Qp[Bc * Hc * Sc * Dc];
__device__ float g_Kp[Bc * Hc * Sc * Dc];
__device__ float g_Vp[Bc * Hc * Sc * Dc];
__device__ float g_Ao[Bc * Sc * DMc];

// ---------------------------------------------------------------------------
// GEMM: C[M=8192, N=512] = X[M,512] @ W[512,512] + bias (fp32 FFMA)
// ---------------------------------------------------------------------------
template <bool SPLIT>
__global__ __launch_bounds__(256, 2)
void gemm512(const float* __restrict__ X, const float* __restrict__ W,
             const float* __restrict__ bias, float* __restrict__ out)
{
    __shared__ float As[16][132];
    __shared__ float Bs[16][132];

    const int tid = threadIdx.x;
    const int tx  = tid & 15;
    const int ty  = tid >> 4;
    const int m0  = blockIdx.y << 7;
    const int n0  = blockIdx.x << 7;

    float acc[8][8];
#pragma unroll
    for (int i = 0; i < 8; i++)
#pragma unroll
        for (int j = 0; j < 8; j++) acc[i][j] = 0.f;

    for (int k0 = 0; k0 < DMc; k0 += 16) {
#pragma unroll
        for (int p = 0; p < 2; p++) {
            int f  = tid + (p << 8);
            int r  = f >> 2;
            int c4 = (f & 3) << 2;
            float4 v = *(const float4*)(X + (m0 + r) * DMc + k0 + c4);
            As[c4 + 0][r] = v.x;
            As[c4 + 1][r] = v.y;
            As[c4 + 2][r] = v.z;
            As[c4 + 3][r] = v.w;
        }
#pragma unroll
        for (int p = 0; p < 2; p++) {
            int f  = tid + (p << 8);
            int kr = f >> 5;
            int n4 = (f & 31) << 2;
            *(float4*)&Bs[kr][n4] =
                *(const float4*)(W + (k0 + kr) * DMc + n0 + n4);
        }
        __syncthreads();

#pragma unroll
        for (int kk = 0; kk < 16; kk++) {
            float a[8], b[8];
            *(float4*)(a)     = *(const float4*)&As[kk][ty * 8];
            *(float4*)(a + 4) = *(const float4*)&As[kk][ty * 8 + 4];
            *(float4*)(b)     = *(const float4*)&Bs[kk][tx * 8];
            *(float4*)(b + 4) = *(const float4*)&Bs[kk][tx * 8 + 4];
#pragma unroll
            for (int i = 0; i < 8; i++)
#pragma unroll
                for (int j = 0; j < 8; j++)
                    acc[i][j] += a[i] * b[j];
        }
        __syncthreads();
    }

#pragma unroll
    for (int i = 0; i < 8; i++) {
        int m  = m0 + ty * 8 + i;
        int b_ = m >> 12;
        int s_ = m & (Sc - 1);
#pragma unroll
        for (int j4 = 0; j4 < 8; j4 += 4) {
            int n = n0 + tx * 8 + j4;
            float4 v;
            v.x = acc[i][j4 + 0] + bias[n + 0];
            v.y = acc[i][j4 + 1] + bias[n + 1];
            v.z = acc[i][j4 + 2] + bias[n + 2];
            v.w = acc[i][j4 + 3] + bias[n + 3];
            if (SPLIT) {
                int h = n >> 6;
                int d = n & 63;
                *(float4*)(out + ((b_ * Hc + h) * Sc + s_) * Dc + d) = v;
            } else {
                *(float4*)(out + m * DMc + n) = v;
            }
        }
    }
}

// ---------------------------------------------------------------------------
// Flash attention, tf32 mma.sync m16n8k8, register-resident online softmax.
// Block: 128 threads (4 warps), BQ=128 (32 rows/warp), BK=64, D=64.
// smem:
//   Qs[128][68] tf32 (Q pre-scaled by 0.125)     -- A frags, bank 4g+tig CF
//   Ks[64][68]  tf32 [key][d]                    -- QK B frags, bank 4g+tig CF
//   Vs[64][72]  tf32 [key][d]                    -- PV B frags, bank 8tig+g CF
//   mk[64]      mask * -1e9
// P stays in registers: C-frag -> A-frag via 8 shuffles per 8-key block.
// ---------------------------------------------------------------------------
#define QS_STR 68
#define KS_STR 68
#define VS_STR 72
#define QS_OFF 0
#define KS_OFF (128 * QS_STR)
#define VS_OFF (KS_OFF + 64 * KS_STR)
#define MK_OFF (VS_OFF + 64 * VS_STR)
#define ATTN_SMEM_FLOATS (MK_OFF + 64)
#define ATTN_SMEM_BYTES  (ATTN_SMEM_FLOATS * 4)

__device__ __forceinline__ unsigned f2tf32(float x) {
    unsigned r;
    asm("cvt.rna.tf32.f32 %0, %1;" : "=r"(r) : "f"(x));
    return r;
}

__device__ __forceinline__ void mma_tf32(float c[4], unsigned a0, unsigned a1,
                                         unsigned a2, unsigned a3,
                                         unsigned b0, unsigned b1) {
    asm volatile(
        "mma.sync.aligned.m16n8k8.row.col.f32.tf32.tf32.f32 "
        "{%0,%1,%2,%3}, {%4,%5,%6,%7}, {%8,%9}, {%0,%1,%2,%3};\n"
        : "+f"(c[0]), "+f"(c[1]), "+f"(c[2]), "+f"(c[3])
        : "r"(a0), "r"(a1), "r"(a2), "r"(a3), "r"(b0), "r"(b1));
}

__global__ __launch_bounds__(128, 2)
void attn_mma(const float* __restrict__ Qp, const float* __restrict__ Kp,
              const float* __restrict__ Vp, const float* __restrict__ mask,
              float* __restrict__ Ao)
{
    extern __shared__ float sm[];
    unsigned* Qs = (unsigned*)(sm + QS_OFF);
    unsigned* Ks = (unsigned*)(sm + KS_OFF);
    unsigned* Vs = (unsigned*)(sm + VS_OFF);
    float*    mk = sm + MK_OFF;

    const int tid  = threadIdx.x;
    const int wid  = tid >> 5;
    const int lane = tid & 31;
    const int g    = lane >> 2;
    const int tig  = lane & 3;
    const int wm   = wid << 5;          // warp's 32-row base

    const int bh = blockIdx.y;
    const int b  = bh >> 3;
    const int h  = bh & 7;
    const int q0 = blockIdx.x << 7;

    const float* Qb = Qp + ((size_t)bh * Sc + q0) * Dc;
    const float* Kb = Kp + (size_t)bh * Sc * Dc;
    const float* Vb = Vp + (size_t)bh * Sc * Dc;

    // ---- load Q tile (128x64), scale, convert, conflict-free uint4 STS ----
#pragma unroll
    for (int p = 0; p < 16; p++) {
        int idx = tid + (p << 7);
        int r   = idx >> 4;
        int c4  = (idx & 15) << 2;
        float4 v = *(const float4*)(Qb + r * Dc + c4);
        uint4 u = make_uint4(f2tf32(v.x * 0.125f), f2tf32(v.y * 0.125f),
                             f2tf32(v.z * 0.125f), f2tf32(v.w * 0.125f));
        *(uint4*)&Qs[r * QS_STR + c4] = u;
    }

    // state: index [mt*2 + half], rows wm+mt*16+g (half 0) and +8 (half 1)
    float m_i[4] = {-INFINITY, -INFINITY, -INFINITY, -INFINITY};
    float l_i[4] = {0.f, 0.f, 0.f, 0.f};
    float o[2][8][4];
#pragma unroll
    for (int mt = 0; mt < 2; mt++)
#pragma unroll
        for (int nt = 0; nt < 8; nt++)
#pragma unroll
            for (int j = 0; j < 4; j++) o[mt][nt][j] = 0.f;

    const int  L0  = (g << 2) + (tig >> 1);
    const int  L2  = L0 + 2;
    const bool odd = tig & 1;

    for (int k0 = 0; k0 < Sc; k0 += 64) {
        // ---- K/V tile load + tf32 convert, natural [key][d], uint4 STS ----
#pragma unroll
        for (int p = 0; p < 8; p++) {
            int idx = tid + (p << 7);
            int r   = idx >> 4;
            int c4  = (idx & 15) << 2;
            float4 kv = *(const float4*)(Kb + (size_t)(k0 + r) * Dc + c4);
            float4 vv = *(const float4*)(Vb + (size_t)(k0 + r) * Dc + c4);
            *(uint4*)&Ks[r * KS_STR + c4] =
                make_uint4(f2tf32(kv.x), f2tf32(kv.y), f2tf32(kv.z), f2tf32(kv.w));
            *(uint4*)&Vs[r * VS_STR + c4] =
                make_uint4(f2tf32(vv.x), f2tf32(vv.y), f2tf32(vv.z), f2tf32(vv.w));
        }
        if (tid < 16) {
            float4 mv = *(const float4*)(mask + (size_t)b * Sc + k0 + tid * 4);
            *(float4*)&mk[tid * 4] = make_float4(mv.x * -1e9f, mv.y * -1e9f,
                                                 mv.z * -1e9f, mv.w * -1e9f);
        }
        __syncthreads();

        // ---- S = Q @ K^T (accumulators in registers) ----
        float c[2][8][4];
#pragma unroll
        for (int mt = 0; mt < 2; mt++)
#pragma unroll
            for (int nt = 0; nt < 8; nt++)
#pragma unroll
                for (int j = 0; j < 4; j++) c[mt][nt][j] = 0.f;

#pragma unroll
        for (int kk = 0; kk < 8; kk++) {
            int kb = (kk << 3) + tig;
            unsigned a[2][4];
#pragma unroll
            for (int mt = 0; mt < 2; mt++) {
                int r0 = wm + (mt << 4) + g;
                a[mt][0] = Qs[r0 * QS_STR + kb];
                a[mt][1] = Qs[(r0 + 8) * QS_STR + kb];
                a[mt][2] = Qs[r0 * QS_STR + kb + 4];
                a[mt][3] = Qs[(r0 + 8) * QS_STR + kb + 4];
            }
#pragma unroll
            for (int nt = 0; nt < 8; nt++) {
                unsigned b0 = Ks[((nt << 3) + g) * KS_STR + kb];
                unsigned b1 = Ks[((nt << 3) + g) * KS_STR + kb + 4];
                mma_tf32(c[0][nt], a[0][0], a[0][1], a[0][2], a[0][3], b0, b1);
                mma_tf32(c[1][nt], a[1][0], a[1][1], a[1][2], a[1][3], b0, b1);
            }
        }

        // ---- mask + online softmax, fully in registers ----
#pragma unroll
        for (int mt = 0; mt < 2; mt++) {
            float vmax0 = -INFINITY, vmax1 = -INFINITY;
#pragma unroll
            for (int nt = 0; nt < 8; nt++) {
                float2 mv = *(const float2*)&mk[(nt << 3) + (tig << 1)];
                c[mt][nt][0] += mv.x; c[mt][nt][1] += mv.y;
                c[mt][nt][2] += mv.x; c[mt][nt][3] += mv.y;
                vmax0 = fmaxf(vmax0, fmaxf(c[mt][nt][0], c[mt][nt][1]));
                vmax1 = fmaxf(vmax1, fmaxf(c[mt][nt][2], c[mt][nt][3]));
            }
            vmax0 = fmaxf(vmax0, __shfl_xor_sync(0xffffffffu, vmax0, 1));
            vmax0 = fmaxf(vmax0, __shfl_xor_sync(0xffffffffu, vmax0, 2));
            vmax1 = fmaxf(vmax1, __shfl_xor_sync(0xffffffffu, vmax1, 1));
            vmax1 = fmaxf(vmax1, __shfl_xor_sync(0xffffffffu, vmax1, 2));

            float mn0 = fmaxf(m_i[mt * 2 + 0], vmax0);
            float mn1 = fmaxf(m_i[mt * 2 + 1], vmax1);
            float al0 = __expf(m_i[mt * 2 + 0] - mn0);
            float al1 = __expf(m_i[mt * 2 + 1] - mn1);
            m_i[mt * 2 + 0] = mn0;
            m_i[mt * 2 + 1] = mn1;

            float rs0 = 0.f, rs1 = 0.f;
#pragma unroll
            for (int nt = 0; nt < 8; nt++) {
                float p0 = __expf(c[mt][nt][0] - mn0);
                float p1 = __expf(c[mt][nt][1] - mn0);
                float p2 = __expf(c[mt][nt][2] - mn1);
                float p3 = __expf(c[mt][nt][3] - mn1);
                rs0 += p0 + p1;
                rs1 += p2 + p3;
                c[mt][nt][0] = __uint_as_float(f2tf32(p0));
                c[mt][nt][1] = __uint_as_float(f2tf32(p1));
                c[mt][nt][2] = __uint_as_float(f2tf32(p2));
                c[mt][nt][3] = __uint_as_float(f2tf32(p3));
            }
            rs0 += __shfl_xor_sync(0xffffffffu, rs0, 1);
            rs0 += __shfl_xor_sync(0xffffffffu, rs0, 2);
            rs1 += __shfl_xor_sync(0xffffffffu, rs1, 1);
            rs1 += __shfl_xor_sync(0xffffffffu, rs1, 2);
            l_i[mt * 2 + 0] = l_i[mt * 2 + 0] * al0 + rs0;
            l_i[mt * 2 + 1] = l_i[mt * 2 + 1] * al1 + rs1;

#pragma unroll
            for (int nt = 0; nt < 8; nt++) {
                o[mt][nt][0] *= al0; o[mt][nt][1] *= al0;
                o[mt][nt][2] *= al1; o[mt][nt][3] *= al1;
            }
        }

        // ---- O += P @ V  (P A-frags via shuffle transpose of C-frags) ----
#pragma unroll
        for (int kk = 0; kk < 8; kk++) {
            unsigned a[2][4];
#pragma unroll
            for (int mt = 0; mt < 2; mt++) {
                float x0 = __shfl_sync(0xffffffffu, c[mt][kk][0], L0);
                float x1 = __shfl_sync(0xffffffffu, c[mt][kk][1], L0);
                float y0 = __shfl_sync(0xffffffffu, c[mt][kk][2], L0);
                float y1 = __shfl_sync(0xffffffffu, c[mt][kk][3], L0);
                float z0 = __shfl_sync(0xffffffffu, c[mt][kk][0], L2);
                float z1 = __shfl_sync(0xffffffffu, c[mt][kk][1], L2);
                float w0 = __shfl_sync(0xffffffffu, c[mt][kk][2], L2);
                float w1 = __shfl_sync(0xffffffffu, c[mt][kk][3], L2);
                a[mt][0] = __float_as_uint(odd ? x1 : x0);
                a[mt][1] = __float_as_uint(odd ? y1 : y0);
                a[mt][2] = __float_as_uint(odd ? z1 : z0);
                a[mt][3] = __float_as_uint(odd ? w1 : w0);
            }
            int kr = (kk << 3) + tig;
#pragma unroll
            for (int nt = 0; nt < 8; nt++) {
                unsigned b0 = Vs[kr * VS_STR + (nt << 3) + g];
                unsigned b1 = Vs[(kr + 4) * VS_STR + (nt << 3) + g];
                mma_tf32(o[0][nt], a[0][0], a[0][1], a[0][2], a[0][3], b0, b1);
                mma_tf32(o[1][nt], a[1][0], a[1][1], a[1][2], a[1][3], b0, b1);
            }
        }
        __syncthreads();
    }

    // ---- epilogue: normalize, write [B, S, DM] ----
#pragma unroll
    for (int mt = 0; mt < 2; mt++) {
        float inv0 = 1.f / l_i[mt * 2 + 0];
        float inv1 = 1.f / l_i[mt * 2 + 1];
        int r0 = q0 + wm + (mt << 4) + g;
#pragma unroll
        for (int nt = 0; nt < 8; nt++) {
            int d = (nt << 3) + (tig << 1);
            *(float2*)(Ao + ((size_t)b * Sc + r0) * DMc + h * Dc + d) =
                make_float2(o[mt][nt][0] * inv0, o[mt][nt][1] * inv0);
            *(float2*)(Ao + ((size_t)b * Sc + r0 + 8) * DMc + h * Dc + d) =
                make_float2(o[mt][nt][2] * inv1, o[mt][nt][3] * inv1);
        }
    }
}

// ---------------------------------------------------------------------------
extern "C" void kernel_launch(void* const* d_in, const int* in_sizes, int n_in,
                              void* d_out, int out_size)
{
    const float* q    = (const float*)d_in[0];
    const float* k    = (const float*)d_in[1];
    const float* v    = (const float*)d_in[2];
    const float* mask = (const float*)d_in[3];
    const float* Wq   = (const float*)d_in[4];
    const float* bq   = (const float*)d_in[5];
    const float* Wk   = (const float*)d_in[6];
    const float* bk   = (const float*)d_in[7];
    const float* Wv   = (const float*)d_in[8];
    const float* bv   = (const float*)d_in[9];
    const float* Wo   = (const float*)d_in[10];
    const float* bo   = (const float*)d_in[11];
    float* out = (float*)d_out;

    float *Qp, *Kp, *Vp, *Ao;
    cudaGetSymbolAddress((void**)&Qp, g_Qp);
    cudaGetSymbolAddress((void**)&Kp, g_Kp);
    cudaGetSymbolAddress((void**)&Vp, g_Vp);
    cudaGetSymbolAddress((void**)&Ao, g_Ao);

    cudaFuncSetAttribute(attn_mma, cudaFuncAttributeMaxDynamicSharedMemorySize,
                         ATTN_SMEM_BYTES);

    dim3 gg(DMc / 128, Mc / 128);   // (4, 64)
    gemm512<true><<<gg, 256>>>(q, Wq, bq, Qp);
    gemm512<true><<<gg, 256>>>(k, Wk, bk, Kp);
    gemm512<true><<<gg, 256>>>(v, Wv, bv, Vp);

    dim3 ga(Sc / 128, Bc * Hc);     // (32, 16)
    attn_mma<<<ga, 128, ATTN_SMEM_BYTES>>>(Qp, Kp, Vp, mask, Ao);

    gemm512<false><<<gg, 256>>>(Ao, Wo, bo, out);
}

// round 4
// speedup vs baseline: 3.3117x; 1.3245x over previous
#include <cuda_runtime.h>
#include <cuda_fp16.h>
#include <math.h>

#define Bc  2
#define Sc  4096
#define DMc 512
#define Hc  8
#define Dc  64
#define Mc  (Bc * Sc)   // 8192

// Scratch: projected Q/K/V in [B*H, S, D] layout, attention output in [B, S, DM].
__device__ float g_Qp[Bc * Hc * Sc * Dc];
__device__ float g_Kp[Bc * Hc * Sc * Dc];
__device__ float g_Vp[Bc * Hc * Sc * Dc];
__device__ float g_Ao[Bc * Sc * DMc];

// ---------------------------------------------------------------------------
// Merged QKV projection GEMM: blockIdx.z selects (X, W, bias, out).
// C[M=8192, N=512] = X @ W + bias, head-split output layout.
// ---------------------------------------------------------------------------
__global__ __launch_bounds__(256, 2)
void gemm_qkv(const float* __restrict__ q, const float* __restrict__ k,
              const float* __restrict__ v,
              const float* __restrict__ Wq, const float* __restrict__ Wk,
              const float* __restrict__ Wv,
              const float* __restrict__ bq, const float* __restrict__ bk,
              const float* __restrict__ bv,
              float* __restrict__ Qp, float* __restrict__ Kp,
              float* __restrict__ Vp)
{
    const int z = blockIdx.z;
    const float* X    = z == 0 ? q  : (z == 1 ? k  : v);
    const float* W    = z == 0 ? Wq : (z == 1 ? Wk : Wv);
    const float* bias = z == 0 ? bq : (z == 1 ? bk : bv);
    float*       out  = z == 0 ? Qp : (z == 1 ? Kp : Vp);

    __shared__ float As[16][132];
    __shared__ float Bs[16][132];

    const int tid = threadIdx.x;
    const int tx  = tid & 15;
    const int ty  = tid >> 4;
    const int m0  = blockIdx.y << 7;
    const int n0  = blockIdx.x << 7;

    float acc[8][8];
#pragma unroll
    for (int i = 0; i < 8; i++)
#pragma unroll
        for (int j = 0; j < 8; j++) acc[i][j] = 0.f;

    for (int k0 = 0; k0 < DMc; k0 += 16) {
#pragma unroll
        for (int p = 0; p < 2; p++) {
            int f  = tid + (p << 8);
            int r  = f >> 2;
            int c4 = (f & 3) << 2;
            float4 vv = *(const float4*)(X + (m0 + r) * DMc + k0 + c4);
            As[c4 + 0][r] = vv.x;
            As[c4 + 1][r] = vv.y;
            As[c4 + 2][r] = vv.z;
            As[c4 + 3][r] = vv.w;
        }
#pragma unroll
        for (int p = 0; p < 2; p++) {
            int f  = tid + (p << 8);
            int kr = f >> 5;
            int n4 = (f & 31) << 2;
            *(float4*)&Bs[kr][n4] =
                *(const float4*)(W + (k0 + kr) * DMc + n0 + n4);
        }
        __syncthreads();

#pragma unroll
        for (int kk = 0; kk < 16; kk++) {
            float a[8], b[8];
            *(float4*)(a)     = *(const float4*)&As[kk][ty * 8];
            *(float4*)(a + 4) = *(const float4*)&As[kk][ty * 8 + 4];
            *(float4*)(b)     = *(const float4*)&Bs[kk][tx * 8];
            *(float4*)(b + 4) = *(const float4*)&Bs[kk][tx * 8 + 4];
#pragma unroll
            for (int i = 0; i < 8; i++)
#pragma unroll
                for (int j = 0; j < 8; j++)
                    acc[i][j] += a[i] * b[j];
        }
        __syncthreads();
    }

#pragma unroll
    for (int i = 0; i < 8; i++) {
        int m  = m0 + ty * 8 + i;
        int b_ = m >> 12;
        int s_ = m & (Sc - 1);
#pragma unroll
        for (int j4 = 0; j4 < 8; j4 += 4) {
            int n = n0 + tx * 8 + j4;
            float4 vv;
            vv.x = acc[i][j4 + 0] + bias[n + 0];
            vv.y = acc[i][j4 + 1] + bias[n + 1];
            vv.z = acc[i][j4 + 2] + bias[n + 2];
            vv.w = acc[i][j4 + 3] + bias[n + 3];
            int h = n >> 6;
            int d = n & 63;
            *(float4*)(out + ((b_ * Hc + h) * Sc + s_) * Dc + d) = vv;
        }
    }
}

// ---------------------------------------------------------------------------
// Output projection GEMM (row-major output).
// ---------------------------------------------------------------------------
__global__ __launch_bounds__(256, 2)
void gemm_out(const float* __restrict__ X, const float* __restrict__ W,
              const float* __restrict__ bias, float* __restrict__ out)
{
    __shared__ float As[16][132];
    __shared__ float Bs[16][132];

    const int tid = threadIdx.x;
    const int tx  = tid & 15;
    const int ty  = tid >> 4;
    const int m0  = blockIdx.y << 7;
    const int n0  = blockIdx.x << 7;

    float acc[8][8];
#pragma unroll
    for (int i = 0; i < 8; i++)
#pragma unroll
        for (int j = 0; j < 8; j++) acc[i][j] = 0.f;

    for (int k0 = 0; k0 < DMc; k0 += 16) {
#pragma unroll
        for (int p = 0; p < 2; p++) {
            int f  = tid + (p << 8);
            int r  = f >> 2;
            int c4 = (f & 3) << 2;
            float4 vv = *(const float4*)(X + (m0 + r) * DMc + k0 + c4);
            As[c4 + 0][r] = vv.x;
            As[c4 + 1][r] = vv.y;
            As[c4 + 2][r] = vv.z;
            As[c4 + 3][r] = vv.w;
        }
#pragma unroll
        for (int p = 0; p < 2; p++) {
            int f  = tid + (p << 8);
            int kr = f >> 5;
            int n4 = (f & 31) << 2;
            *(float4*)&Bs[kr][n4] =
                *(const float4*)(W + (k0 + kr) * DMc + n0 + n4);
        }
        __syncthreads();

#pragma unroll
        for (int kk = 0; kk < 16; kk++) {
            float a[8], b[8];
            *(float4*)(a)     = *(const float4*)&As[kk][ty * 8];
            *(float4*)(a + 4) = *(const float4*)&As[kk][ty * 8 + 4];
            *(float4*)(b)     = *(const float4*)&Bs[kk][tx * 8];
            *(float4*)(b + 4) = *(const float4*)&Bs[kk][tx * 8 + 4];
#pragma unroll
            for (int i = 0; i < 8; i++)
#pragma unroll
                for (int j = 0; j < 8; j++)
                    acc[i][j] += a[i] * b[j];
        }
        __syncthreads();
    }

#pragma unroll
    for (int i = 0; i < 8; i++) {
        int m = m0 + ty * 8 + i;
#pragma unroll
        for (int j4 = 0; j4 < 8; j4 += 4) {
            int n = n0 + tx * 8 + j4;
            float4 vv;
            vv.x = acc[i][j4 + 0] + bias[n + 0];
            vv.y = acc[i][j4 + 1] + bias[n + 1];
            vv.z = acc[i][j4 + 2] + bias[n + 2];
            vv.w = acc[i][j4 + 3] + bias[n + 3];
            *(float4*)(out + m * DMc + n) = vv;
        }
    }
}

// ---------------------------------------------------------------------------
// Flash attention, fp16 mma.sync m16n8k16 (fp32 accum) + ldmatrix.
// Block: 128 threads (4 warps), BQ=128 (32 rows/warp), BK=64, D=64.
// smem (half, row stride 72 -> LDSM conflict-free):
//   Qs[128][72]  (Q pre-scaled by 0.125*log2e)
//   Ks[64][72]   natural [key][d]
//   Vs[64][72]   natural [key][d]; B-frags via ldmatrix.x4.trans
//   mk[64] float: mask * (-1e9*log2e)
// Softmax in log2 domain (ex2.approx). P C-frags -> A-frags via f16x2 pack.
// ---------------------------------------------------------------------------
#define HSTR 72
#define QS_HALVES (128 * HSTR)
#define KS_HALVES (64 * HSTR)
#define VS_HALVES (64 * HSTR)
#define MK_BYTE_OFF ((QS_HALVES + KS_HALVES + VS_HALVES) * 2)
#define ATTN_SMEM_BYTES (MK_BYTE_OFF + 64 * 4)

#define SCL (0.125f * 1.44269504f)
#define MSK (-1.44269504e9f)

__device__ __forceinline__ float ex2(float x) {
    float r;
    asm("ex2.approx.f32 %0, %1;" : "=f"(r) : "f"(x));
    return r;
}

__device__ __forceinline__ unsigned pack_f16x2(float lo, float hi) {
    unsigned r;
    asm("cvt.rn.f16x2.f32 %0, %1, %2;" : "=r"(r) : "f"(hi), "f"(lo));
    return r;
}

__device__ __forceinline__ void ldsm_x4(unsigned& r0, unsigned& r1,
                                        unsigned& r2, unsigned& r3,
                                        unsigned addr) {
    asm volatile("ldmatrix.sync.aligned.m8n8.x4.shared.b16 {%0,%1,%2,%3}, [%4];"
                 : "=r"(r0), "=r"(r1), "=r"(r2), "=r"(r3) : "r"(addr));
}

__device__ __forceinline__ void ldsm_x4_t(unsigned& r0, unsigned& r1,
                                          unsigned& r2, unsigned& r3,
                                          unsigned addr) {
    asm volatile("ldmatrix.sync.aligned.m8n8.x4.trans.shared.b16 {%0,%1,%2,%3}, [%4];"
                 : "=r"(r0), "=r"(r1), "=r"(r2), "=r"(r3) : "r"(addr));
}

__device__ __forceinline__ void mma_f16(float c[4], unsigned a0, unsigned a1,
                                        unsigned a2, unsigned a3,
                                        unsigned b0, unsigned b1) {
    asm volatile(
        "mma.sync.aligned.m16n8k16.row.col.f32.f16.f16.f32 "
        "{%0,%1,%2,%3}, {%4,%5,%6,%7}, {%8,%9}, {%0,%1,%2,%3};\n"
        : "+f"(c[0]), "+f"(c[1]), "+f"(c[2]), "+f"(c[3])
        : "r"(a0), "r"(a1), "r"(a2), "r"(a3), "r"(b0), "r"(b1));
}

__global__ __launch_bounds__(128, 2)
void attn_f16(const float* __restrict__ Qp, const float* __restrict__ Kp,
              const float* __restrict__ Vp, const float* __restrict__ mask,
              float* __restrict__ Ao)
{
    extern __shared__ __align__(16) char smc[];
    __half* Qs = (__half*)smc;
    __half* Ks = Qs + QS_HALVES;
    __half* Vs = Ks + KS_HALVES;
    float*  mk = (float*)(smc + MK_BYTE_OFF);

    const unsigned qs_b = (unsigned)__cvta_generic_to_shared(Qs);
    const unsigned ks_b = (unsigned)__cvta_generic_to_shared(Ks);
    const unsigned vs_b = (unsigned)__cvta_generic_to_shared(Vs);

    const int tid  = threadIdx.x;
    const int wid  = tid >> 5;
    const int lane = tid & 31;
    const int g    = lane >> 2;
    const int tig  = lane & 3;
    const int wm   = wid << 5;          // warp's 32-row base

    // ldmatrix per-lane row/col pattern (shared by all three operand loads)
    const int lrow = (lane & 7) + ((lane >> 3) & 1) * 8;
    const int lcol = (lane >> 4) << 3;

    const int bh = blockIdx.y;
    const int b  = bh >> 3;
    const int h  = bh & 7;
    const int q0 = blockIdx.x << 7;

    const float* Qb = Qp + ((size_t)bh * Sc + q0) * Dc;
    const float* Kb = Kp + (size_t)bh * Sc * Dc;
    const float* Vb = Vp + (size_t)bh * Sc * Dc;

    // ---- load Q tile (128x64), scale into log2 domain, fp16 convert ----
#pragma unroll
    for (int p = 0; p < 16; p++) {
        int idx = tid + (p << 7);
        int r   = idx >> 4;
        int c4  = (idx & 15) << 2;
        float4 v = *(const float4*)(Qb + r * Dc + c4);
        uint2 u = make_uint2(pack_f16x2(v.x * SCL, v.y * SCL),
                             pack_f16x2(v.z * SCL, v.w * SCL));
        *(uint2*)&Qs[r * HSTR + c4] = u;
    }

    float m_i[4] = {-INFINITY, -INFINITY, -INFINITY, -INFINITY};
    float l_i[4] = {0.f, 0.f, 0.f, 0.f};
    float o[2][8][4];
#pragma unroll
    for (int mt = 0; mt < 2; mt++)
#pragma unroll
        for (int nt = 0; nt < 8; nt++)
#pragma unroll
            for (int j = 0; j < 4; j++) o[mt][nt][j] = 0.f;

    for (int k0 = 0; k0 < Sc; k0 += 64) {
        // ---- K/V tile load + fp16 convert, natural [key][d] ----
#pragma unroll
        for (int p = 0; p < 8; p++) {
            int idx = tid + (p << 7);
            int r   = idx >> 4;
            int c4  = (idx & 15) << 2;
            float4 kv = *(const float4*)(Kb + (size_t)(k0 + r) * Dc + c4);
            float4 vv = *(const float4*)(Vb + (size_t)(k0 + r) * Dc + c4);
            *(uint2*)&Ks[r * HSTR + c4] =
                make_uint2(pack_f16x2(kv.x, kv.y), pack_f16x2(kv.z, kv.w));
            *(uint2*)&Vs[r * HSTR + c4] =
                make_uint2(pack_f16x2(vv.x, vv.y), pack_f16x2(vv.z, vv.w));
        }
        if (tid < 16) {
            float4 mv = *(const float4*)(mask + (size_t)b * Sc + k0 + tid * 4);
            *(float4*)&mk[tid * 4] = make_float4(mv.x * MSK, mv.y * MSK,
                                                 mv.z * MSK, mv.w * MSK);
        }
        __syncthreads();

        // ---- S = Q @ K^T (log2-domain logits in fp32 C frags) ----
        float c[2][8][4];
#pragma unroll
        for (int mt = 0; mt < 2; mt++)
#pragma unroll
            for (int nt = 0; nt < 8; nt++)
#pragma unroll
                for (int j = 0; j < 4; j++) c[mt][nt][j] = 0.f;

#pragma unroll
        for (int kb4 = 0; kb4 < 4; kb4++) {
            const int kb = kb4 << 4;
            unsigned a[2][4];
#pragma unroll
            for (int mt = 0; mt < 2; mt++) {
                unsigned addr = qs_b +
                    (((wm + (mt << 4) + lrow) * HSTR) + kb + lcol) * 2;
                ldsm_x4(a[mt][0], a[mt][1], a[mt][2], a[mt][3], addr);
            }
#pragma unroll
            for (int np = 0; np < 4; np++) {
                unsigned addr = ks_b +
                    ((((np << 4) + lrow) * HSTR) + kb + lcol) * 2;
                unsigned b0e, b0o, b1e, b1o;
                ldsm_x4(b0e, b0o, b1e, b1o, addr);
                mma_f16(c[0][2 * np],     a[0][0], a[0][1], a[0][2], a[0][3], b0e, b1e);
                mma_f16(c[0][2 * np + 1], a[0][0], a[0][1], a[0][2], a[0][3], b0o, b1o);
                mma_f16(c[1][2 * np],     a[1][0], a[1][1], a[1][2], a[1][3], b0e, b1e);
                mma_f16(c[1][2 * np + 1], a[1][0], a[1][1], a[1][2], a[1][3], b0o, b1o);
            }
        }

        // ---- mask + online softmax (log2 domain), in registers ----
#pragma unroll
        for (int mt = 0; mt < 2; mt++) {
            float vmax0 = -INFINITY, vmax1 = -INFINITY;
#pragma unroll
            for (int nt = 0; nt < 8; nt++) {
                float2 mv = *(const float2*)&mk[(nt << 3) + (tig << 1)];
                c[mt][nt][0] += mv.x; c[mt][nt][1] += mv.y;
                c[mt][nt][2] += mv.x; c[mt][nt][3] += mv.y;
                vmax0 = fmaxf(vmax0, fmaxf(c[mt][nt][0], c[mt][nt][1]));
                vmax1 = fmaxf(vmax1, fmaxf(c[mt][nt][2], c[mt][nt][3]));
            }
            vmax0 = fmaxf(vmax0, __shfl_xor_sync(0xffffffffu, vmax0, 1));
            vmax0 = fmaxf(vmax0, __shfl_xor_sync(0xffffffffu, vmax0, 2));
            vmax1 = fmaxf(vmax1, __shfl_xor_sync(0xffffffffu, vmax1, 1));
            vmax1 = fmaxf(vmax1, __shfl_xor_sync(0xffffffffu, vmax1, 2));

            float mn0 = fmaxf(m_i[mt * 2 + 0], vmax0);
            float mn1 = fmaxf(m_i[mt * 2 + 1], vmax1);
            float al0 = ex2(m_i[mt * 2 + 0] - mn0);
            float al1 = ex2(m_i[mt * 2 + 1] - mn1);
            m_i[mt * 2 + 0] = mn0;
            m_i[mt * 2 + 1] = mn1;

            float rs0 = 0.f, rs1 = 0.f;
#pragma unroll
            for (int nt = 0; nt < 8; nt++) {
                float p0 = ex2(c[mt][nt][0] - mn0);
                float p1 = ex2(c[mt][nt][1] - mn0);
                float p2 = ex2(c[mt][nt][2] - mn1);
                float p3 = ex2(c[mt][nt][3] - mn1);
                rs0 += p0 + p1;
                rs1 += p2 + p3;
                c[mt][nt][0] = p0; c[mt][nt][1] = p1;
                c[mt][nt][2] = p2; c[mt][nt][3] = p3;
            }
            rs0 += __shfl_xor_sync(0xffffffffu, rs0, 1);
            rs0 += __shfl_xor_sync(0xffffffffu, rs0, 2);
            rs1 += __shfl_xor_sync(0xffffffffu, rs1, 1);
            rs1 += __shfl_xor_sync(0xffffffffu, rs1, 2);
            l_i[mt * 2 + 0] = l_i[mt * 2 + 0] * al0 + rs0;
            l_i[mt * 2 + 1] = l_i[mt * 2 + 1] * al1 + rs1;

#pragma unroll
            for (int nt = 0; nt < 8; nt++) {
                o[mt][nt][0] *= al0; o[mt][nt][1] *= al0;
                o[mt][nt][2] *= al1; o[mt][nt][3] *= al1;
            }
        }

        // ---- O += P @ V (P A-frags = packed C-frags, V via ldsm.trans) ----
#pragma unroll
        for (int kb4 = 0; kb4 < 4; kb4++) {
            unsigned pa[2][4];
#pragma unroll
            for (int mt = 0; mt < 2; mt++) {
                pa[mt][0] = pack_f16x2(c[mt][2 * kb4][0],     c[mt][2 * kb4][1]);
                pa[mt][1] = pack_f16x2(c[mt][2 * kb4][2],     c[mt][2 * kb4][3]);
                pa[mt][2] = pack_f16x2(c[mt][2 * kb4 + 1][0], c[mt][2 * kb4 + 1][1]);
                pa[mt][3] = pack_f16x2(c[mt][2 * kb4 + 1][2], c[mt][2 * kb4 + 1][3]);
            }
#pragma unroll
            for (int dp = 0; dp < 4; dp++) {
                unsigned addr = vs_b +
                    ((((kb4 << 4) + lrow) * HSTR) + (dp << 4) + lcol) * 2;
                unsigned r0, r1, r2, r3;
                ldsm_x4_t(r0, r1, r2, r3, addr);
                mma_f16(o[0][2 * dp],     pa[0][0], pa[0][1], pa[0][2], pa[0][3], r0, r1);
                mma_f16(o[0][2 * dp + 1], pa[0][0], pa[0][1], pa[0][2], pa[0][3], r2, r3);
                mma_f16(o[1][2 * dp],     pa[1][0], pa[1][1], pa[1][2], pa[1][3], r0, r1);
                mma_f16(o[1][2 * dp + 1], pa[1][0], pa[1][1], pa[1][2], pa[1][3], r2, r3);
            }
        }
        __syncthreads();
    }

    // ---- epilogue: normalize, write [B, S, DM] ----
#pragma unroll
    for (int mt = 0; mt < 2; mt++) {
        float inv0 = 1.f / l_i[mt * 2 + 0];
        float inv1 = 1.f / l_i[mt * 2 + 1];
        int r0 = q0 + wm + (mt << 4) + g;
#pragma unroll
        for (int nt = 0; nt < 8; nt++) {
            int d = (nt << 3) + (tig << 1);
            *(float2*)(Ao + ((size_t)b * Sc + r0) * DMc + h * Dc + d) =
                make_float2(o[mt][nt][0] * inv0, o[mt][nt][1] * inv0);
            *(float2*)(Ao + ((size_t)b * Sc + r0 + 8) * DMc + h * Dc + d) =
                make_float2(o[mt][nt][2] * inv1, o[mt][nt][3] * inv1);
        }
    }
}

// ---------------------------------------------------------------------------
extern "C" void kernel_launch(void* const* d_in, const int* in_sizes, int n_in,
                              void* d_out, int out_size)
{
    const float* q    = (const float*)d_in[0];
    const float* k    = (const float*)d_in[1];
    const float* v    = (const float*)d_in[2];
    const float* mask = (const float*)d_in[3];
    const float* Wq   = (const float*)d_in[4];
    const float* bq   = (const float*)d_in[5];
    const float* Wk   = (const float*)d_in[6];
    const float* bk   = (const float*)d_in[7];
    const float* Wv   = (const float*)d_in[8];
    const float* bv   = (const float*)d_in[9];
    const float* Wo   = (const float*)d_in[10];
    const float* bo   = (const float*)d_in[11];
    float* out = (float*)d_out;

    float *Qp, *Kp, *Vp, *Ao;
    cudaGetSymbolAddress((void**)&Qp, g_Qp);
    cudaGetSymbolAddress((void**)&Kp, g_Kp);
    cudaGetSymbolAddress((void**)&Vp, g_Vp);
    cudaGetSymbolAddress((void**)&Ao, g_Ao);

    cudaFuncSetAttribute(attn_f16, cudaFuncAttributeMaxDynamicSharedMemorySize,
                         ATTN_SMEM_BYTES);

    dim3 gqkv(DMc / 128, Mc / 128, 3);   // (4, 64, 3)
    gemm_qkv<<<gqkv, 256>>>(q, k, v, Wq, Wk, Wv, bq, bk, bv, Qp, Kp, Vp);

    dim3 ga(Sc / 128, Bc * Hc);          // (32, 16)
    attn_f16<<<ga, 128, ATTN_SMEM_BYTES>>>(Qp, Kp, Vp, mask, Ao);

    dim3 gg(DMc / 128, Mc / 128);        // (4, 64)
    gemm_out<<<gg, 256>>>(Ao, Wo, bo, out);
}

// round 5
// speedup vs baseline: 5.8012x; 1.7517x over previous
#include <cuda_runtime.h>
#include <cuda_fp16.h>
#include <math.h>

#define Bc  2
#define Sc  4096
#define DMc 512
#define Hc  8
#define Dc  64
#define Mc  (Bc * Sc)   // 8192

// Scratch: projected Q/K/V in [B*H, S, D] layout, attention output in [B, S, DM].
__device__ float g_Qp[Bc * Hc * Sc * Dc];
__device__ float g_Kp[Bc * Hc * Sc * Dc];
__device__ float g_Vp[Bc * Hc * Sc * Dc];
__device__ float g_Ao[Bc * Sc * DMc];

// ---------------------------------------------------------------------------
// Common mma/ldmatrix helpers
// ---------------------------------------------------------------------------
__device__ __forceinline__ unsigned pack_f16x2(float lo, float hi) {
    unsigned r;
    asm("cvt.rn.f16x2.f32 %0, %1, %2;" : "=r"(r) : "f"(hi), "f"(lo));
    return r;
}

__device__ __forceinline__ void ldsm_x4(unsigned& r0, unsigned& r1,
                                        unsigned& r2, unsigned& r3,
                                        unsigned addr) {
    asm volatile("ldmatrix.sync.aligned.m8n8.x4.shared.b16 {%0,%1,%2,%3}, [%4];"
                 : "=r"(r0), "=r"(r1), "=r"(r2), "=r"(r3) : "r"(addr));
}

__device__ __forceinline__ void ldsm_x4_t(unsigned& r0, unsigned& r1,
                                          unsigned& r2, unsigned& r3,
                                          unsigned addr) {
    asm volatile("ldmatrix.sync.aligned.m8n8.x4.trans.shared.b16 {%0,%1,%2,%3}, [%4];"
                 : "=r"(r0), "=r"(r1), "=r"(r2), "=r"(r3) : "r"(addr));
}

__device__ __forceinline__ void mma_f16(float c[4], unsigned a0, unsigned a1,
                                        unsigned a2, unsigned a3,
                                        unsigned b0, unsigned b1) {
    asm volatile(
        "mma.sync.aligned.m16n8k16.row.col.f32.f16.f16.f32 "
        "{%0,%1,%2,%3}, {%4,%5,%6,%7}, {%8,%9}, {%0,%1,%2,%3};\n"
        : "+f"(c[0]), "+f"(c[1]), "+f"(c[2]), "+f"(c[3])
        : "r"(a0), "r"(a1), "r"(a2), "r"(a3), "r"(b0), "r"(b1));
}

// ---------------------------------------------------------------------------
// fp16 tensor-core GEMM: C[M=8192, N=512] = X @ W + bias (fp32 accum).
// Block 128x128, BK=32, 8 warps (4 m x 2 n), warp tile 32x64.
// Double-buffered smem; A[m][k] stride 40 halves, B[k][n] stride 136 halves
// (both ldmatrix conflict-free).  SPLIT: head-split output layout.
// ---------------------------------------------------------------------------
#define ASTR 40
#define BSTR 136
#define A_HALVES (128 * ASTR)
#define B_HALVES (32 * BSTR)
#define STAGE_HALVES (A_HALVES + B_HALVES)

template <bool SPLIT>
__device__ __forceinline__ void gemm_f16_body(
    const float* __restrict__ X, const float* __restrict__ W,
    const float* __restrict__ bias, float* __restrict__ out)
{
    __shared__ __align__(16) __half sh[2 * STAGE_HALVES];

    const int tid  = threadIdx.x;
    const int wid  = tid >> 5;
    const int lane = tid & 31;
    const int g    = lane >> 2;
    const int tig  = lane & 3;
    const int wm   = (wid & 3) << 5;     // 0,32,64,96
    const int wn   = (wid >> 2) << 6;    // 0,64
    const int lrow = (lane & 7) + ((lane >> 3) & 1) * 8;
    const int lcol = (lane >> 4) << 3;

    const int m0 = blockIdx.y << 7;
    const int n0 = blockIdx.x << 7;

    const unsigned sh_b = (unsigned)__cvta_generic_to_shared(sh);

    float c[2][8][4];
#pragma unroll
    for (int mt = 0; mt < 2; mt++)
#pragma unroll
        for (int nt = 0; nt < 8; nt++)
#pragma unroll
            for (int j = 0; j < 4; j++) c[mt][nt][j] = 0.f;

    // chunk loader: global fp32 -> fp16 smem stage
    auto load_chunk = [&](int k0, int buf) {
        __half* As = sh + buf * STAGE_HALVES;
        __half* Bs = As + A_HALVES;
#pragma unroll
        for (int p = 0; p < 4; p++) {
            int idx = tid + (p << 8);
            int r   = idx >> 3;            // 0..127
            int c4  = (idx & 7) << 2;      // 0..28
            float4 v = *(const float4*)(X + (size_t)(m0 + r) * DMc + k0 + c4);
            *(uint2*)&As[r * ASTR + c4] =
                make_uint2(pack_f16x2(v.x, v.y), pack_f16x2(v.z, v.w));
        }
#pragma unroll
        for (int p = 0; p < 4; p++) {
            int idx = tid + (p << 8);
            int r   = idx >> 5;            // 0..31
            int c4  = (idx & 31) << 2;     // 0..124
            float4 v = *(const float4*)(W + (size_t)(k0 + r) * DMc + n0 + c4);
            *(uint2*)&Bs[r * BSTR + c4] =
                make_uint2(pack_f16x2(v.x, v.y), pack_f16x2(v.z, v.w));
        }
    };

    load_chunk(0, 0);
    __syncthreads();

    int buf = 0;
    for (int k0 = 0; k0 < DMc; k0 += 32) {
        if (k0 + 32 < DMc) load_chunk(k0 + 32, buf ^ 1);

        const unsigned as_b = sh_b + buf * STAGE_HALVES * 2;
        const unsigned bs_b = as_b + A_HALVES * 2;

#pragma unroll
        for (int ks = 0; ks < 2; ks++) {
            const int kb = ks << 4;
            unsigned a[2][4];
#pragma unroll
            for (int mt = 0; mt < 2; mt++) {
                unsigned addr = as_b +
                    (((wm + (mt << 4) + lrow) * ASTR) + kb + lcol) * 2;
                ldsm_x4(a[mt][0], a[mt][1], a[mt][2], a[mt][3], addr);
            }
#pragma unroll
            for (int np = 0; np < 4; np++) {
                unsigned addr = bs_b +
                    (((kb + lrow) * BSTR) + wn + (np << 4) + lcol) * 2;
                unsigned r0, r1, r2, r3;
                ldsm_x4_t(r0, r1, r2, r3, addr);
                mma_f16(c[0][2 * np],     a[0][0], a[0][1], a[0][2], a[0][3], r0, r1);
                mma_f16(c[0][2 * np + 1], a[0][0], a[0][1], a[0][2], a[0][3], r2, r3);
                mma_f16(c[1][2 * np],     a[1][0], a[1][1], a[1][2], a[1][3], r0, r1);
                mma_f16(c[1][2 * np + 1], a[1][0], a[1][1], a[1][2], a[1][3], r2, r3);
            }
        }
        __syncthreads();
        buf ^= 1;
    }

    // ---- epilogue ----
    const int b_ = m0 >> 12;             // batch (block never straddles)
#pragma unroll
    for (int mt = 0; mt < 2; mt++) {
        int m = m0 + wm + (mt << 4) + g;
        int s_ = m & (Sc - 1);
#pragma unroll
        for (int nt = 0; nt < 8; nt++) {
            int n = n0 + wn + (nt << 3) + (tig << 1);
            float bx = bias[n], by = bias[n + 1];
            float2 v0 = make_float2(c[mt][nt][0] + bx, c[mt][nt][1] + by);
            float2 v1 = make_float2(c[mt][nt][2] + bx, c[mt][nt][3] + by);
            if (SPLIT) {
                int h = n >> 6;
                int d = n & 63;
                float* base = out + ((size_t)(b_ * Hc + h) * Sc) * Dc + d;
                *(float2*)(base + (size_t)s_ * Dc)       = v0;
                *(float2*)(base + (size_t)(s_ + 8) * Dc) = v1;
            } else {
                *(float2*)(out + (size_t)m * DMc + n)       = v0;
                *(float2*)(out + (size_t)(m + 8) * DMc + n) = v1;
            }
        }
    }
}

__global__ __launch_bounds__(256, 2)
void gemm_qkv(const float* __restrict__ q, const float* __restrict__ k,
              const float* __restrict__ v,
              const float* __restrict__ Wq, const float* __restrict__ Wk,
              const float* __restrict__ Wv,
              const float* __restrict__ bq, const float* __restrict__ bk,
              const float* __restrict__ bv,
              float* __restrict__ Qp, float* __restrict__ Kp,
              float* __restrict__ Vp)
{
    const int z = blockIdx.z;
    const float* X    = z == 0 ? q  : (z == 1 ? k  : v);
    const float* W    = z == 0 ? Wq : (z == 1 ? Wk : Wv);
    const float* bias = z == 0 ? bq : (z == 1 ? bk : bv);
    float*       out  = z == 0 ? Qp : (z == 1 ? Kp : Vp);
    gemm_f16_body<true>(X, W, bias, out);
}

__global__ __launch_bounds__(256, 2)
void gemm_out(const float* __restrict__ X, const float* __restrict__ W,
              const float* __restrict__ bias, float* __restrict__ out)
{
    gemm_f16_body<false>(X, W, bias, out);
}

// ---------------------------------------------------------------------------
// Flash attention, fp16 mma.sync m16n8k16 (fp32 accum) + ldmatrix.
// Block: 128 threads (4 warps), BQ=128 (32 rows/warp), BK=64, D=64.
// smem (half, row stride 72 -> LDSM conflict-free):
//   Qs[128][72]  (Q pre-scaled by 0.125*log2e)
//   Ks[64][72]   natural [key][d]
//   Vs[64][72]   natural [key][d]; B-frags via ldmatrix.x4.trans
//   mk[64] float: mask * (-1e9*log2e)
// Softmax in log2 domain (ex2.approx). P C-frags -> A-frags via f16x2 pack.
// ---------------------------------------------------------------------------
#define HSTR 72
#define QS_HALVES (128 * HSTR)
#define KS_HALVES (64 * HSTR)
#define VS_HALVES (64 * HSTR)
#define MK_BYTE_OFF ((QS_HALVES + KS_HALVES + VS_HALVES) * 2)
#define ATTN_SMEM_BYTES (MK_BYTE_OFF + 64 * 4)

#define SCL (0.125f * 1.44269504f)
#define MSK (-1.44269504e9f)

__device__ __forceinline__ float ex2(float x) {
    float r;
    asm("ex2.approx.f32 %0, %1;" : "=f"(r) : "f"(x));
    return r;
}

__global__ __launch_bounds__(128, 2)
void attn_f16(const float* __restrict__ Qp, const float* __restrict__ Kp,
              const float* __restrict__ Vp, const float* __restrict__ mask,
              float* __restrict__ Ao)
{
    extern __shared__ __align__(16) char smc[];
    __half* Qs = (__half*)smc;
    __half* Ks = Qs + QS_HALVES;
    __half* Vs = Ks + KS_HALVES;
    float*  mk = (float*)(smc + MK_BYTE_OFF);

    const unsigned qs_b = (unsigned)__cvta_generic_to_shared(Qs);
    const unsigned ks_b = (unsigned)__cvta_generic_to_shared(Ks);
    const unsigned vs_b = (unsigned)__cvta_generic_to_shared(Vs);

    const int tid  = threadIdx.x;
    const int wid  = tid >> 5;
    const int lane = tid & 31;
    const int g    = lane >> 2;
    const int tig  = lane & 3;
    const int wm   = wid << 5;

    const int lrow = (lane & 7) + ((lane >> 3) & 1) * 8;
    const int lcol = (lane >> 4) << 3;

    const int bh = blockIdx.y;
    const int b  = bh >> 3;
    const int h  = bh & 7;
    const int q0 = blockIdx.x << 7;

    const float* Qb = Qp + ((size_t)bh * Sc + q0) * Dc;
    const float* Kb = Kp + (size_t)bh * Sc * Dc;
    const float* Vb = Vp + (size_t)bh * Sc * Dc;

#pragma unroll
    for (int p = 0; p < 16; p++) {
        int idx = tid + (p << 7);
        int r   = idx >> 4;
        int c4  = (idx & 15) << 2;
        float4 v = *(const float4*)(Qb + r * Dc + c4);
        uint2 u = make_uint2(pack_f16x2(v.x * SCL, v.y * SCL),
                             pack_f16x2(v.z * SCL, v.w * SCL));
        *(uint2*)&Qs[r * HSTR + c4] = u;
    }

    float m_i[4] = {-INFINITY, -INFINITY, -INFINITY, -INFINITY};
    float l_i[4] = {0.f, 0.f, 0.f, 0.f};
    float o[2][8][4];
#pragma unroll
    for (int mt = 0; mt < 2; mt++)
#pragma unroll
        for (int nt = 0; nt < 8; nt++)
#pragma unroll
            for (int j = 0; j < 4; j++) o[mt][nt][j] = 0.f;

    for (int k0 = 0; k0 < Sc; k0 += 64) {
#pragma unroll
        for (int p = 0; p < 8; p++) {
            int idx = tid + (p << 7);
            int r   = idx >> 4;
            int c4  = (idx & 15) << 2;
            float4 kv = *(const float4*)(Kb + (size_t)(k0 + r) * Dc + c4);
            float4 vv = *(const float4*)(Vb + (size_t)(k0 + r) * Dc + c4);
            *(uint2*)&Ks[r * HSTR + c4] =
                make_uint2(pack_f16x2(kv.x, kv.y), pack_f16x2(kv.z, kv.w));
            *(uint2*)&Vs[r * HSTR + c4] =
                make_uint2(pack_f16x2(vv.x, vv.y), pack_f16x2(vv.z, vv.w));
        }
        if (tid < 16) {
            float4 mv = *(const float4*)(mask + (size_t)b * Sc + k0 + tid * 4);
            *(float4*)&mk[tid * 4] = make_float4(mv.x * MSK, mv.y * MSK,
                                                 mv.z * MSK, mv.w * MSK);
        }
        __syncthreads();

        float c[2][8][4];
#pragma unroll
        for (int mt = 0; mt < 2; mt++)
#pragma unroll
            for (int nt = 0; nt < 8; nt++)
#pragma unroll
                for (int j = 0; j < 4; j++) c[mt][nt][j] = 0.f;

#pragma unroll
        for (int kb4 = 0; kb4 < 4; kb4++) {
            const int kb = kb4 << 4;
            unsigned a[2][4];
#pragma unroll
            for (int mt = 0; mt < 2; mt++) {
                unsigned addr = qs_b +
                    (((wm + (mt << 4) + lrow) * HSTR) + kb + lcol) * 2;
                ldsm_x4(a[mt][0], a[mt][1], a[mt][2], a[mt][3], addr);
            }
#pragma unroll
            for (int np = 0; np < 4; np++) {
                unsigned addr = ks_b +
                    ((((np << 4) + lrow) * HSTR) + kb + lcol) * 2;
                unsigned b0e, b0o, b1e, b1o;
                ldsm_x4(b0e, b0o, b1e, b1o, addr);
                mma_f16(c[0][2 * np],     a[0][0], a[0][1], a[0][2], a[0][3], b0e, b1e);
                mma_f16(c[0][2 * np + 1], a[0][0], a[0][1], a[0][2], a[0][3], b0o, b1o);
                mma_f16(c[1][2 * np],     a[1][0], a[1][1], a[1][2], a[1][3], b0e, b1e);
                mma_f16(c[1][2 * np + 1], a[1][0], a[1][1], a[1][2], a[1][3], b0o, b1o);
            }
        }

#pragma unroll
        for (int mt = 0; mt < 2; mt++) {
            float vmax0 = -INFINITY, vmax1 = -INFINITY;
#pragma unroll
            for (int nt = 0; nt < 8; nt++) {
                float2 mv = *(const float2*)&mk[(nt << 3) + (tig << 1)];
                c[mt][nt][0] += mv.x; c[mt][nt][1] += mv.y;
                c[mt][nt][2] += mv.x; c[mt][nt][3] += mv.y;
                vmax0 = fmaxf(vmax0, fmaxf(c[mt][nt][0], c[mt][nt][1]));
                vmax1 = fmaxf(vmax1, fmaxf(c[mt][nt][2], c[mt][nt][3]));
            }
            vmax0 = fmaxf(vmax0, __shfl_xor_sync(0xffffffffu, vmax0, 1));
            vmax0 = fmaxf(vmax0, __shfl_xor_sync(0xffffffffu, vmax0, 2));
            vmax1 = fmaxf(vmax1, __shfl_xor_sync(0xffffffffu, vmax1, 1));
            vmax1 = fmaxf(vmax1, __shfl_xor_sync(0xffffffffu, vmax1, 2));

            float mn0 = fmaxf(m_i[mt * 2 + 0], vmax0);
            float mn1 = fmaxf(m_i[mt * 2 + 1], vmax1);
            float al0 = ex2(m_i[mt * 2 + 0] - mn0);
            float al1 = ex2(m_i[mt * 2 + 1] - mn1);
            m_i[mt * 2 + 0] = mn0;
            m_i[mt * 2 + 1] = mn1;

            float rs0 = 0.f, rs1 = 0.f;
#pragma unroll
            for (int nt = 0; nt < 8; nt++) {
                float p0 = ex2(c[mt][nt][0] - mn0);
                float p1 = ex2(c[mt][nt][1] - mn0);
                float p2 = ex2(c[mt][nt][2] - mn1);
                float p3 = ex2(c[mt][nt][3] - mn1);
                rs0 += p0 + p1;
                rs1 += p2 + p3;
                c[mt][nt][0] = p0; c[mt][nt][1] = p1;
                c[mt][nt][2] = p2; c[mt][nt][3] = p3;
            }
            rs0 += __shfl_xor_sync(0xffffffffu, rs0, 1);
            rs0 += __shfl_xor_sync(0xffffffffu, rs0, 2);
            rs1 += __shfl_xor_sync(0xffffffffu, rs1, 1);
            rs1 += __shfl_xor_sync(0xffffffffu, rs1, 2);
            l_i[mt * 2 + 0] = l_i[mt * 2 + 0] * al0 + rs0;
            l_i[mt * 2 + 1] = l_i[mt * 2 + 1] * al1 + rs1;

#pragma unroll
            for (int nt = 0; nt < 8; nt++) {
                o[mt][nt][0] *= al0; o[mt][nt][1] *= al0;
                o[mt][nt][2] *= al1; o[mt][nt][3] *= al1;
            }
        }

#pragma unroll
        for (int kb4 = 0; kb4 < 4; kb4++) {
            unsigned pa[2][4];
#pragma unroll
            for (int mt = 0; mt < 2; mt++) {
                pa[mt][0] = pack_f16x2(c[mt][2 * kb4][0],     c[mt][2 * kb4][1]);
                pa[mt][1] = pack_f16x2(c[mt][2 * kb4][2],     c[mt][2 * kb4][3]);
                pa[mt][2] = pack_f16x2(c[mt][2 * kb4 + 1][0], c[mt][2 * kb4 + 1][1]);
                pa[mt][3] = pack_f16x2(c[mt][2 * kb4 + 1][2], c[mt][2 * kb4 + 1][3]);
            }
#pragma unroll
            for (int dp = 0; dp < 4; dp++) {
                unsigned addr = vs_b +
                    ((((kb4 << 4) + lrow) * HSTR) + (dp << 4) + lcol) * 2;
                unsigned r0, r1, r2, r3;
                ldsm_x4_t(r0, r1, r2, r3, addr);
                mma_f16(o[0][2 * dp],     pa[0][0], pa[0][1], pa[0][2], pa[0][3], r0, r1);
                mma_f16(o[0][2 * dp + 1], pa[0][0], pa[0][1], pa[0][2], pa[0][3], r2, r3);
                mma_f16(o[1][2 * dp],     pa[1][0], pa[1][1], pa[1][2], pa[1][3], r0, r1);
                mma_f16(o[1][2 * dp + 1], pa[1][0], pa[1][1], pa[1][2], pa[1][3], r2, r3);
            }
        }
        __syncthreads();
    }

#pragma unroll
    for (int mt = 0; mt < 2; mt++) {
        float inv0 = 1.f / l_i[mt * 2 + 0];
        float inv1 = 1.f / l_i[mt * 2 + 1];
        int r0 = q0 + wm + (mt << 4) + g;
#pragma unroll
        for (int nt = 0; nt < 8; nt++) {
            int d = (nt << 3) + (tig << 1);
            *(float2*)(Ao + ((size_t)b * Sc + r0) * DMc + h * Dc + d) =
                make_float2(o[mt][nt][0] * inv0, o[mt][nt][1] * inv0);
            *(float2*)(Ao + ((size_t)b * Sc + r0 + 8) * DMc + h * Dc + d) =
                make_float2(o[mt][nt][2] * inv1, o[mt][nt][3] * inv1);
        }
    }
}

// ---------------------------------------------------------------------------
extern "C" void kernel_launch(void* const* d_in, const int* in_sizes, int n_in,
                              void* d_out, int out_size)
{
    const float* q    = (const float*)d_in[0];
    const float* k    = (const float*)d_in[1];
    const float* v    = (const float*)d_in[2];
    const float* mask = (const float*)d_in[3];
    const float* Wq   = (const float*)d_in[4];
    const float* bq   = (const float*)d_in[5];
    const float* Wk   = (const float*)d_in[6];
    const float* bk   = (const float*)d_in[7];
    const float* Wv   = (const float*)d_in[8];
    const float* bv   = (const float*)d_in[9];
    const float* Wo   = (const float*)d_in[10];
    const float* bo   = (const float*)d_in[11];
    float* out = (float*)d_out;

    float *Qp, *Kp, *Vp, *Ao;
    cudaGetSymbolAddress((void**)&Qp, g_Qp);
    cudaGetSymbolAddress((void**)&Kp, g_Kp);
    cudaGetSymbolAddress((void**)&Vp, g_Vp);
    cudaGetSymbolAddress((void**)&Ao, g_Ao);

    cudaFuncSetAttribute(attn_f16, cudaFuncAttributeMaxDynamicSharedMemorySize,
                         ATTN_SMEM_BYTES);

    dim3 gqkv(DMc / 128, Mc / 128, 3);   // (4, 64, 3)
    gemm_qkv<<<gqkv, 256>>>(q, k, v, Wq, Wk, Wv, bq, bk, bv, Qp, Kp, Vp);

    dim3 ga(Sc / 128, Bc * Hc);          // (32, 16)
    attn_f16<<<ga, 128, ATTN_SMEM_BYTES>>>(Qp, Kp, Vp, mask, Ao);

    dim3 gg(DMc / 128, Mc / 128);        // (4, 64)
    gemm_out<<<gg, 256>>>(Ao, Wo, bo, out);
}

// round 6
// speedup vs baseline: 6.8866x; 1.1871x over previous
#include <cuda_runtime.h>
#include <cuda_fp16.h>
#include <math.h>

#define Bc  2
#define Sc  4096
#define DMc 512
#define Hc  8
#define Dc  64
#define Mc  (Bc * Sc)   // 8192

#define SCL (0.125f * 1.44269504f)
#define MSK (-1.44269504e9f)

// fp16 mirrors of inputs/weights + fp16 scratch
__device__ __half g_qh[Mc * DMc];
__device__ __half g_kh[Mc * DMc];
__device__ __half g_vh[Mc * DMc];
__device__ __half g_Wqh[DMc * DMc];
__device__ __half g_Wkh[DMc * DMc];
__device__ __half g_Wvh[DMc * DMc];
__device__ __half g_Woh[DMc * DMc];
__device__ __half g_Qp[Bc * Hc * Sc * Dc];
__device__ __half g_Kp[Bc * Hc * Sc * Dc];
__device__ __half g_Vp[Bc * Hc * Sc * Dc];
__device__ __half g_Ao[Mc * DMc];

// ---------------------------------------------------------------------------
// helpers
// ---------------------------------------------------------------------------
__device__ __forceinline__ unsigned pack_f16x2(float lo, float hi) {
    unsigned r;
    asm("cvt.rn.f16x2.f32 %0, %1, %2;" : "=r"(r) : "f"(hi), "f"(lo));
    return r;
}

__device__ __forceinline__ float ex2(float x) {
    float r;
    asm("ex2.approx.f32 %0, %1;" : "=f"(r) : "f"(x));
    return r;
}

__device__ __forceinline__ void cp16(unsigned dst, const void* src) {
    asm volatile("cp.async.cg.shared.global [%0], [%1], 16;"
                 :: "r"(dst), "l"(__cvta_generic_to_global(src)));
}
__device__ __forceinline__ void cp_commit() {
    asm volatile("cp.async.commit_group;");
}
template <int N>
__device__ __forceinline__ void cp_wait() {
    asm volatile("cp.async.wait_group %0;" :: "n"(N));
}

__device__ __forceinline__ void ldsm_x4(unsigned& r0, unsigned& r1,
                                        unsigned& r2, unsigned& r3,
                                        unsigned addr) {
    asm volatile("ldmatrix.sync.aligned.m8n8.x4.shared.b16 {%0,%1,%2,%3}, [%4];"
                 : "=r"(r0), "=r"(r1), "=r"(r2), "=r"(r3) : "r"(addr));
}
__device__ __forceinline__ void ldsm_x4_t(unsigned& r0, unsigned& r1,
                                          unsigned& r2, unsigned& r3,
                                          unsigned addr) {
    asm volatile("ldmatrix.sync.aligned.m8n8.x4.trans.shared.b16 {%0,%1,%2,%3}, [%4];"
                 : "=r"(r0), "=r"(r1), "=r"(r2), "=r"(r3) : "r"(addr));
}
__device__ __forceinline__ void mma_f16(float c[4], unsigned a0, unsigned a1,
                                        unsigned a2, unsigned a3,
                                        unsigned b0, unsigned b1) {
    asm volatile(
        "mma.sync.aligned.m16n8k16.row.col.f32.f16.f16.f32 "
        "{%0,%1,%2,%3}, {%4,%5,%6,%7}, {%8,%9}, {%0,%1,%2,%3};\n"
        : "+f"(c[0]), "+f"(c[1]), "+f"(c[2]), "+f"(c[3])
        : "r"(a0), "r"(a1), "r"(a2), "r"(a3), "r"(b0), "r"(b1));
}

// ---------------------------------------------------------------------------
// fp32 -> fp16 conversion pre-pass
// ---------------------------------------------------------------------------
__global__ __launch_bounds__(256)
void cvt_in(const float* __restrict__ q, const float* __restrict__ k,
            const float* __restrict__ v,
            __half* __restrict__ qh, __half* __restrict__ kh,
            __half* __restrict__ vh)
{
    const int z = blockIdx.z;
    const float* s = z == 0 ? q  : (z == 1 ? k  : v);
    __half*      d = z == 0 ? qh : (z == 1 ? kh : vh);
    int i = blockIdx.x * 256 + threadIdx.x;          // float4 index
    float4 f = ((const float4*)s)[i];
    ((uint2*)d)[i] = make_uint2(pack_f16x2(f.x, f.y), pack_f16x2(f.z, f.w));
}

__global__ __launch_bounds__(256)
void cvt_w(const float* __restrict__ Wq, const float* __restrict__ Wk,
           const float* __restrict__ Wv, const float* __restrict__ Wo,
           __half* __restrict__ Wqh, __half* __restrict__ Wkh,
           __half* __restrict__ Wvh, __half* __restrict__ Woh)
{
    const int z = blockIdx.z;
    const float* s = z == 0 ? Wq  : (z == 1 ? Wk  : (z == 2 ? Wv  : Wo));
    __half*      d = z == 0 ? Wqh : (z == 1 ? Wkh : (z == 2 ? Wvh : Woh));
    int i = blockIdx.x * 256 + threadIdx.x;
    float4 f = ((const float4*)s)[i];
    ((uint2*)d)[i] = make_uint2(pack_f16x2(f.x, f.y), pack_f16x2(f.z, f.w));
}

// ---------------------------------------------------------------------------
// pure-fp16 GEMM, cp.async double-buffered. C = X @ W (+bias) [*scale].
// Block 128x128, BK=32, 8 warps (4m x 2n), warp tile 32x64.
// MODE 0: __half out, head-split layout, scale applied.
// MODE 1: float out, row-major.
// ---------------------------------------------------------------------------
#define ASTR 40
#define BSTR 136
#define A_BYTES (128 * ASTR * 2)
#define B_BYTES (32 * BSTR * 2)
#define STAGE_BYTES (A_BYTES + B_BYTES)

template <int MODE>
__device__ __forceinline__ void gemm_f16_body(
    const __half* __restrict__ X, const __half* __restrict__ W,
    const float* __restrict__ bias, void* outp, float scale)
{
    __shared__ __align__(16) char sh[2 * STAGE_BYTES];

    const int tid  = threadIdx.x;
    const int wid  = tid >> 5;
    const int lane = tid & 31;
    const int g    = lane >> 2;
    const int tig  = lane & 3;
    const int wm   = (wid & 3) << 5;
    const int wn   = (wid >> 2) << 6;
    const int lrow = (lane & 7) + ((lane >> 3) & 1) * 8;
    const int lcol = (lane >> 4) << 3;

    const int m0 = blockIdx.y << 7;
    const int n0 = blockIdx.x << 7;

    const unsigned sh_b = (unsigned)__cvta_generic_to_shared(sh);

    float c[2][8][4];
#pragma unroll
    for (int mt = 0; mt < 2; mt++)
#pragma unroll
        for (int nt = 0; nt < 8; nt++)
#pragma unroll
            for (int j = 0; j < 4; j++) c[mt][nt][j] = 0.f;

    auto issue = [&](int k0, int s) {
        unsigned as = sh_b + s * STAGE_BYTES;
        unsigned bs = as + A_BYTES;
#pragma unroll
        for (int p = 0; p < 2; p++) {
            int i = tid + (p << 8);
            int r = i >> 2, cc = (i & 3) << 3;
            cp16(as + (r * ASTR + cc) * 2, X + (size_t)(m0 + r) * DMc + k0 + cc);
        }
#pragma unroll
        for (int p = 0; p < 2; p++) {
            int i = tid + (p << 8);
            int r = i >> 4, cc = (i & 15) << 3;
            cp16(bs + (r * BSTR + cc) * 2, W + (size_t)(k0 + r) * DMc + n0 + cc);
        }
        cp_commit();
    };

    issue(0, 0);
    int buf = 0;
    for (int kc = 0; kc < 16; kc++) {
        if (kc < 15) { issue((kc + 1) << 5, buf ^ 1); cp_wait<1>(); }
        else         { cp_wait<0>(); }
        __syncthreads();

        const unsigned as_b = sh_b + buf * STAGE_BYTES;
        const unsigned bs_b = as_b + A_BYTES;
#pragma unroll
        for (int ks = 0; ks < 2; ks++) {
            const int kb = ks << 4;
            unsigned a[2][4];
#pragma unroll
            for (int mt = 0; mt < 2; mt++) {
                unsigned addr = as_b +
                    (((wm + (mt << 4) + lrow) * ASTR) + kb + lcol) * 2;
                ldsm_x4(a[mt][0], a[mt][1], a[mt][2], a[mt][3], addr);
            }
#pragma unroll
            for (int np = 0; np < 4; np++) {
                unsigned addr = bs_b +
                    (((kb + lrow) * BSTR) + wn + (np << 4) + lcol) * 2;
                unsigned r0, r1, r2, r3;
                ldsm_x4_t(r0, r1, r2, r3, addr);
                mma_f16(c[0][2 * np],     a[0][0], a[0][1], a[0][2], a[0][3], r0, r1);
                mma_f16(c[0][2 * np + 1], a[0][0], a[0][1], a[0][2], a[0][3], r2, r3);
                mma_f16(c[1][2 * np],     a[1][0], a[1][1], a[1][2], a[1][3], r0, r1);
                mma_f16(c[1][2 * np + 1], a[1][0], a[1][1], a[1][2], a[1][3], r2, r3);
            }
        }
        __syncthreads();
        buf ^= 1;
    }

    const int b_ = m0 >> 12;
#pragma unroll
    for (int mt = 0; mt < 2; mt++) {
        int m  = m0 + wm + (mt << 4) + g;
        int s_ = m & (Sc - 1);
#pragma unroll
        for (int nt = 0; nt < 8; nt++) {
            int n = n0 + wn + (nt << 3) + (tig << 1);
            float bx = bias[n], by = bias[n + 1];
            if (MODE == 0) {
                __half* out = (__half*)outp;
                int h = n >> 6;
                int d = n & 63;
                unsigned u0 = pack_f16x2((c[mt][nt][0] + bx) * scale,
                                         (c[mt][nt][1] + by) * scale);
                unsigned u1 = pack_f16x2((c[mt][nt][2] + bx) * scale,
                                         (c[mt][nt][3] + by) * scale);
                __half* base = out + ((size_t)(b_ * Hc + h) * Sc) * Dc + d;
                *(unsigned*)(base + (size_t)s_ * Dc)       = u0;
                *(unsigned*)(base + (size_t)(s_ + 8) * Dc) = u1;
            } else {
                float* out = (float*)outp;
                *(float2*)(out + (size_t)m * DMc + n) =
                    make_float2(c[mt][nt][0] + bx, c[mt][nt][1] + by);
                *(float2*)(out + (size_t)(m + 8) * DMc + n) =
                    make_float2(c[mt][nt][2] + bx, c[mt][nt][3] + by);
            }
        }
    }
}

__global__ __launch_bounds__(256, 2)
void gemm_qkv(const __half* __restrict__ qh, const __half* __restrict__ kh,
              const __half* __restrict__ vh,
              const __half* __restrict__ Wqh, const __half* __restrict__ Wkh,
              const __half* __restrict__ Wvh,
              const float* __restrict__ bq, const float* __restrict__ bk,
              const float* __restrict__ bv,
              __half* __restrict__ Qp, __half* __restrict__ Kp,
              __half* __restrict__ Vp)
{
    const int z = blockIdx.z;
    const __half* X    = z == 0 ? qh  : (z == 1 ? kh  : vh);
    const __half* W    = z == 0 ? Wqh : (z == 1 ? Wkh : Wvh);
    const float*  bias = z == 0 ? bq  : (z == 1 ? bk  : bv);
    __half*       out  = z == 0 ? Qp  : (z == 1 ? Kp  : Vp);
    gemm_f16_body<0>(X, W, bias, out, z == 0 ? SCL : 1.0f);
}

__global__ __launch_bounds__(256, 2)
void gemm_out(const __half* __restrict__ X, const __half* __restrict__ W,
              const float* __restrict__ bias, float* __restrict__ out)
{
    gemm_f16_body<1>(X, W, bias, out, 1.0f);
}

// ---------------------------------------------------------------------------
// Flash attention, fp16 mma + ldmatrix, cp.async double-buffered K/V.
// Block: 128 threads (4 warps), BQ=128 (32 rows/warp), BK=64, D=64.
// smem halves: Qs[128][72] | Ks[2][64][72] | Vs[2][64][72] | mk[2][64] float
// ---------------------------------------------------------------------------
#define HSTR 72
#define QS_HALVES (128 * HSTR)
#define KV_STAGE_HALVES (64 * HSTR)
#define KS_HOFF QS_HALVES
#define VS_HOFF (QS_HALVES + 2 * KV_STAGE_HALVES)
#define MK_BYTE_OFF ((QS_HALVES + 4 * KV_STAGE_HALVES) * 2)
#define ATTN_SMEM_BYTES (MK_BYTE_OFF + 2 * 64 * 4)

__global__ __launch_bounds__(128, 2)
void attn_f16(const __half* __restrict__ Qp, const __half* __restrict__ Kp,
              const __half* __restrict__ Vp, const float* __restrict__ mask,
              __half* __restrict__ Ao)
{
    extern __shared__ __align__(16) char smc[];
    __half* Qs = (__half*)smc;
    float*  mk = (float*)(smc + MK_BYTE_OFF);

    const unsigned qs_b = (unsigned)__cvta_generic_to_shared(smc);
    const unsigned ks_b = qs_b + KS_HOFF * 2;
    const unsigned vs_b = qs_b + VS_HOFF * 2;
    const unsigned mk_b = qs_b + MK_BYTE_OFF;

    const int tid  = threadIdx.x;
    const int wid  = tid >> 5;
    const int lane = tid & 31;
    const int g    = lane >> 2;
    const int tig  = lane & 3;
    const int wm   = wid << 5;
    const int lrow = (lane & 7) + ((lane >> 3) & 1) * 8;
    const int lcol = (lane >> 4) << 3;

    const int bh = blockIdx.y;
    const int b  = bh >> 3;
    const int h  = bh & 7;
    const int q0 = blockIdx.x << 7;

    const __half* Qb = Qp + ((size_t)bh * Sc + q0) * Dc;
    const __half* Kb = Kp + (size_t)bh * Sc * Dc;
    const __half* Vb = Vp + (size_t)bh * Sc * Dc;
    const float*  mb = mask + (size_t)b * Sc;

    // stage issuer: K/V tile t (64 rows) + mask slice into stage s
    auto issue = [&](int t, int s) {
        const __half* Kt = Kb + (size_t)(t << 6) * Dc;
        const __half* Vt = Vb + (size_t)(t << 6) * Dc;
        unsigned ks = ks_b + s * KV_STAGE_HALVES * 2;
        unsigned vs = vs_b + s * KV_STAGE_HALVES * 2;
#pragma unroll
        for (int p = 0; p < 4; p++) {
            int i = tid + (p << 7);
            int r = i >> 3, cc = (i & 7) << 3;
            cp16(ks + (r * HSTR + cc) * 2, Kt + r * Dc + cc);
            cp16(vs + (r * HSTR + cc) * 2, Vt + r * Dc + cc);
        }
        if (tid < 16) cp16(mk_b + s * 256 + tid * 16, mb + (t << 6) + tid * 4);
        cp_commit();
    };

    issue(0, 0);

    // Q tile copy (fp16, already scaled by gemm)
#pragma unroll
    for (int p = 0; p < 8; p++) {
        int i = tid + (p << 7);
        int r = i >> 3, cc = (i & 7) << 3;
        *(uint4*)&Qs[r * HSTR + cc] = *(const uint4*)(Qb + r * Dc + cc);
    }

    float m_i[4] = {-INFINITY, -INFINITY, -INFINITY, -INFINITY};
    float l_i[4] = {0.f, 0.f, 0.f, 0.f};
    float o[2][8][4];
#pragma unroll
    for (int mt = 0; mt < 2; mt++)
#pragma unroll
        for (int nt = 0; nt < 8; nt++)
#pragma unroll
            for (int j = 0; j < 4; j++) o[mt][nt][j] = 0.f;

    const int NT = Sc / 64;
    for (int t = 0; t < NT; t++) {
        const int s = t & 1;
        if (t < NT - 1) { issue(t + 1, s ^ 1); cp_wait<1>(); }
        else            { cp_wait<0>(); }
        __syncthreads();

        const unsigned ks_s = ks_b + s * KV_STAGE_HALVES * 2;
        const unsigned vs_s = vs_b + s * KV_STAGE_HALVES * 2;
        const float*   mks  = mk + s * 64;

        // ---- S = Q @ K^T ----
        float c[2][8][4];
#pragma unroll
        for (int mt = 0; mt < 2; mt++)
#pragma unroll
            for (int nt = 0; nt < 8; nt++)
#pragma unroll
                for (int j = 0; j < 4; j++) c[mt][nt][j] = 0.f;

#pragma unroll
        for (int kb4 = 0; kb4 < 4; kb4++) {
            const int kb = kb4 << 4;
            unsigned a[2][4];
#pragma unroll
            for (int mt = 0; mt < 2; mt++) {
                unsigned addr = qs_b +
                    (((wm + (mt << 4) + lrow) * HSTR) + kb + lcol) * 2;
                ldsm_x4(a[mt][0], a[mt][1], a[mt][2], a[mt][3], addr);
            }
#pragma unroll
            for (int np = 0; np < 4; np++) {
                unsigned addr = ks_s +
                    ((((np << 4) + lrow) * HSTR) + kb + lcol) * 2;
                unsigned b0e, b0o, b1e, b1o;
                ldsm_x4(b0e, b0o, b1e, b1o, addr);
                mma_f16(c[0][2 * np],     a[0][0], a[0][1], a[0][2], a[0][3], b0e, b1e);
                mma_f16(c[0][2 * np + 1], a[0][0], a[0][1], a[0][2], a[0][3], b0o, b1o);
                mma_f16(c[1][2 * np],     a[1][0], a[1][1], a[1][2], a[1][3], b0e, b1e);
                mma_f16(c[1][2 * np + 1], a[1][0], a[1][1], a[1][2], a[1][3], b0o, b1o);
            }
        }

        // ---- mask + online softmax (log2 domain) ----
#pragma unroll
        for (int mt = 0; mt < 2; mt++) {
            float vmax0 = -INFINITY, vmax1 = -INFINITY;
#pragma unroll
            for (int nt = 0; nt < 8; nt++) {
                float2 mv = *(const float2*)&mks[(nt << 3) + (tig << 1)];
                c[mt][nt][0] = fmaf(mv.x, MSK, c[mt][nt][0]);
                c[mt][nt][1] = fmaf(mv.y, MSK, c[mt][nt][1]);
                c[mt][nt][2] = fmaf(mv.x, MSK, c[mt][nt][2]);
                c[mt][nt][3] = fmaf(mv.y, MSK, c[mt][nt][3]);
                vmax0 = fmaxf(vmax0, fmaxf(c[mt][nt][0], c[mt][nt][1]));
                vmax1 = fmaxf(vmax1, fmaxf(c[mt][nt][2], c[mt][nt][3]));
            }
            vmax0 = fmaxf(vmax0, __shfl_xor_sync(0xffffffffu, vmax0, 1));
            vmax0 = fmaxf(vmax0, __shfl_xor_sync(0xffffffffu, vmax0, 2));
            vmax1 = fmaxf(vmax1, __shfl_xor_sync(0xffffffffu, vmax1, 1));
            vmax1 = fmaxf(vmax1, __shfl_xor_sync(0xffffffffu, vmax1, 2));

            float mn0 = fmaxf(m_i[mt * 2 + 0], vmax0);
            float mn1 = fmaxf(m_i[mt * 2 + 1], vmax1);
            float al0 = ex2(m_i[mt * 2 + 0] - mn0);
            float al1 = ex2(m_i[mt * 2 + 1] - mn1);
            m_i[mt * 2 + 0] = mn0;
            m_i[mt * 2 + 1] = mn1;

            float rs0 = 0.f, rs1 = 0.f;
#pragma unroll
            for (int nt = 0; nt < 8; nt++) {
                float p0 = ex2(c[mt][nt][0] - mn0);
                float p1 = ex2(c[mt][nt][1] - mn0);
                float p2 = ex2(c[mt][nt][2] - mn1);
                float p3 = ex2(c[mt][nt][3] - mn1);
                rs0 += p0 + p1;
                rs1 += p2 + p3;
                c[mt][nt][0] = p0; c[mt][nt][1] = p1;
                c[mt][nt][2] = p2; c[mt][nt][3] = p3;
            }
            rs0 += __shfl_xor_sync(0xffffffffu, rs0, 1);
            rs0 += __shfl_xor_sync(0xffffffffu, rs0, 2);
            rs1 += __shfl_xor_sync(0xffffffffu, rs1, 1);
            rs1 += __shfl_xor_sync(0xffffffffu, rs1, 2);
            l_i[mt * 2 + 0] = l_i[mt * 2 + 0] * al0 + rs0;
            l_i[mt * 2 + 1] = l_i[mt * 2 + 1] * al1 + rs1;

#pragma unroll
            for (int nt = 0; nt < 8; nt++) {
                o[mt][nt][0] *= al0; o[mt][nt][1] *= al0;
                o[mt][nt][2] *= al1; o[mt][nt][3] *= al1;
            }
        }

        // ---- O += P @ V ----
#pragma unroll
        for (int kb4 = 0; kb4 < 4; kb4++) {
            unsigned pa[2][4];
#pragma unroll
            for (int mt = 0; mt < 2; mt++) {
                pa[mt][0] = pack_f16x2(c[mt][2 * kb4][0],     c[mt][2 * kb4][1]);
                pa[mt][1] = pack_f16x2(c[mt][2 * kb4][2],     c[mt][2 * kb4][3]);
                pa[mt][2] = pack_f16x2(c[mt][2 * kb4 + 1][0], c[mt][2 * kb4 + 1][1]);
                pa[mt][3] = pack_f16x2(c[mt][2 * kb4 + 1][2], c[mt][2 * kb4 + 1][3]);
            }
#pragma unroll
            for (int dp = 0; dp < 4; dp++) {
                unsigned addr = vs_s +
                    ((((kb4 << 4) + lrow) * HSTR) + (dp << 4) + lcol) * 2;
                unsigned r0, r1, r2, r3;
                ldsm_x4_t(r0, r1, r2, r3, addr);
                mma_f16(o[0][2 * dp],     pa[0][0], pa[0][1], pa[0][2], pa[0][3], r0, r1);
                mma_f16(o[0][2 * dp + 1], pa[0][0], pa[0][1], pa[0][2], pa[0][3], r2, r3);
                mma_f16(o[1][2 * dp],     pa[1][0], pa[1][1], pa[1][2], pa[1][3], r0, r1);
                mma_f16(o[1][2 * dp + 1], pa[1][0], pa[1][1], pa[1][2], pa[1][3], r2, r3);
            }
        }
        __syncthreads();
    }

    // ---- epilogue: normalize, write fp16 Ao [B, S, DM] ----
    __half* AoB = Ao + ((size_t)b * Sc) * DMc + h * Dc;
#pragma unroll
    for (int mt = 0; mt < 2; mt++) {
        float inv0 = 1.f / l_i[mt * 2 + 0];
        float inv1 = 1.f / l_i[mt * 2 + 1];
        int r0 = q0 + wm + (mt << 4) + g;
#pragma unroll
        for (int nt = 0; nt < 8; nt++) {
            int d = (nt << 3) + (tig << 1);
            *(unsigned*)(AoB + (size_t)r0 * DMc + d) =
                pack_f16x2(o[mt][nt][0] * inv0, o[mt][nt][1] * inv0);
            *(unsigned*)(AoB + (size_t)(r0 + 8) * DMc + d) =
                pack_f16x2(o[mt][nt][2] * inv1, o[mt][nt][3] * inv1);
        }
    }
}

// ---------------------------------------------------------------------------
extern "C" void kernel_launch(void* const* d_in, const int* in_sizes, int n_in,
                              void* d_out, int out_size)
{
    const float* q    = (const float*)d_in[0];
    const float* k    = (const float*)d_in[1];
    const float* v    = (const float*)d_in[2];
    const float* mask = (const float*)d_in[3];
    const float* Wq   = (const float*)d_in[4];
    const float* bq   = (const float*)d_in[5];
    const float* Wk   = (const float*)d_in[6];
    const float* bk   = (const float*)d_in[7];
    const float* Wv   = (const float*)d_in[8];
    const float* bv   = (const float*)d_in[9];
    const float* Wo   = (const float*)d_in[10];
    const float* bo   = (const float*)d_in[11];
    float* out = (float*)d_out;

    __half *qh, *kh, *vh, *Wqh, *Wkh, *Wvh, *Woh, *Qp, *Kp, *Vp, *Ao;
    cudaGetSymbolAddress((void**)&qh,  g_qh);
    cudaGetSymbolAddress((void**)&kh,  g_kh);
    cudaGetSymbolAddress((void**)&vh,  g_vh);
    cudaGetSymbolAddress((void**)&Wqh, g_Wqh);
    cudaGetSymbolAddress((void**)&Wkh, g_Wkh);
    cudaGetSymbolAddress((void**)&Wvh, g_Wvh);
    cudaGetSymbolAddress((void**)&Woh, g_Woh);
    cudaGetSymbolAddress((void**)&Qp,  g_Qp);
    cudaGetSymbolAddress((void**)&Kp,  g_Kp);
    cudaGetSymbolAddress((void**)&Vp,  g_Vp);
    cudaGetSymbolAddress((void**)&Ao,  g_Ao);

    cudaFuncSetAttribute(attn_f16, cudaFuncAttributeMaxDynamicSharedMemorySize,
                         ATTN_SMEM_BYTES);

    dim3 gin(Mc * DMc / 4 / 256, 1, 3);     // (4096,1,3)
    cvt_in<<<gin, 256>>>(q, k, v, qh, kh, vh);
    dim3 gw(DMc * DMc / 4 / 256, 1, 4);     // (256,1,4)
    cvt_w<<<gw, 256>>>(Wq, Wk, Wv, Wo, Wqh, Wkh, Wvh, Woh);

    dim3 gqkv(DMc / 128, Mc / 128, 3);      // (4, 64, 3)
    gemm_qkv<<<gqkv, 256>>>(qh, kh, vh, Wqh, Wkh, Wvh, bq, bk, bv, Qp, Kp, Vp);

    dim3 ga(Sc / 128, Bc * Hc);             // (32, 16)
    attn_f16<<<ga, 128, ATTN_SMEM_BYTES>>>(Qp, Kp, Vp, mask, Ao);

    dim3 gg(DMc / 128, Mc / 128);           // (4, 64)
    gemm_out<<<gg, 256>>>(Ao, Woh, bo, out);
}

// round 7
// speedup vs baseline: 7.2364x; 1.0508x over previous
#include <cuda_runtime.h>
#include <cuda_fp16.h>
#include <math.h>

#define Bc  2
#define Sc  4096
#define DMc 512
#define Hc  8
#define Dc  64
#define Mc  (Bc * Sc)   // 8192

#define SCL (0.125f * 1.44269504f)
#define MSK (-1.44269504e9f)

// fp16 mirrors of inputs/weights + fp16 scratch
__device__ __half g_qh[Mc * DMc];
__device__ __half g_kh[Mc * DMc];
__device__ __half g_vh[Mc * DMc];
__device__ __half g_Wqh[DMc * DMc];
__device__ __half g_Wkh[DMc * DMc];
__device__ __half g_Wvh[DMc * DMc];
__device__ __half g_Woh[DMc * DMc];
__device__ __half g_Qp[Bc * Hc * Sc * Dc];
__device__ __half g_Kp[Bc * Hc * Sc * Dc];
__device__ __half g_Vp[Bc * Hc * Sc * Dc];
__device__ __half g_Ao[Mc * DMc];

// ---------------------------------------------------------------------------
// helpers
// ---------------------------------------------------------------------------
__device__ __forceinline__ unsigned pack_f16x2(float lo, float hi) {
    unsigned r;
    asm("cvt.rn.f16x2.f32 %0, %1, %2;" : "=r"(r) : "f"(hi), "f"(lo));
    return r;
}

__device__ __forceinline__ float ex2(float x) {
    float r;
    asm("ex2.approx.f32 %0, %1;" : "=f"(r) : "f"(x));
    return r;
}

__device__ __forceinline__ unsigned ex2_f16x2(unsigned x) {
    unsigned r;
    asm("ex2.approx.f16x2 %0, %1;" : "=r"(r) : "r"(x));
    return r;
}

__device__ __forceinline__ void cp16(unsigned dst, const void* src) {
    asm volatile("cp.async.cg.shared.global [%0], [%1], 16;"
                 :: "r"(dst), "l"(__cvta_generic_to_global(src)));
}
__device__ __forceinline__ void cp_commit() {
    asm volatile("cp.async.commit_group;");
}
template <int N>
__device__ __forceinline__ void cp_wait() {
    asm volatile("cp.async.wait_group %0;" :: "n"(N));
}

__device__ __forceinline__ void ldsm_x4(unsigned& r0, unsigned& r1,
                                        unsigned& r2, unsigned& r3,
                                        unsigned addr) {
    asm volatile("ldmatrix.sync.aligned.m8n8.x4.shared.b16 {%0,%1,%2,%3}, [%4];"
                 : "=r"(r0), "=r"(r1), "=r"(r2), "=r"(r3) : "r"(addr));
}
__device__ __forceinline__ void ldsm_x4_t(unsigned& r0, unsigned& r1,
                                          unsigned& r2, unsigned& r3,
                                          unsigned addr) {
    asm volatile("ldmatrix.sync.aligned.m8n8.x4.trans.shared.b16 {%0,%1,%2,%3}, [%4];"
                 : "=r"(r0), "=r"(r1), "=r"(r2), "=r"(r3) : "r"(addr));
}
__device__ __forceinline__ void mma_f16(float c[4], unsigned a0, unsigned a1,
                                        unsigned a2, unsigned a3,
                                        unsigned b0, unsigned b1) {
    asm volatile(
        "mma.sync.aligned.m16n8k16.row.col.f32.f16.f16.f32 "
        "{%0,%1,%2,%3}, {%4,%5,%6,%7}, {%8,%9}, {%0,%1,%2,%3};\n"
        : "+f"(c[0]), "+f"(c[1]), "+f"(c[2]), "+f"(c[3])
        : "r"(a0), "r"(a1), "r"(a2), "r"(a3), "r"(b0), "r"(b1));
}

// ---------------------------------------------------------------------------
// fp32 -> fp16 conversion pre-pass
// ---------------------------------------------------------------------------
__global__ __launch_bounds__(256)
void cvt_in(const float* __restrict__ q, const float* __restrict__ k,
            const float* __restrict__ v,
            __half* __restrict__ qh, __half* __restrict__ kh,
            __half* __restrict__ vh)
{
    const int z = blockIdx.z;
    const float* s = z == 0 ? q  : (z == 1 ? k  : v);
    __half*      d = z == 0 ? qh : (z == 1 ? kh : vh);
    int i = blockIdx.x * 256 + threadIdx.x;          // float4 index
    float4 f = ((const float4*)s)[i];
    ((uint2*)d)[i] = make_uint2(pack_f16x2(f.x, f.y), pack_f16x2(f.z, f.w));
}

__global__ __launch_bounds__(256)
void cvt_w(const float* __restrict__ Wq, const float* __restrict__ Wk,
           const float* __restrict__ Wv, const float* __restrict__ Wo,
           __half* __restrict__ Wqh, __half* __restrict__ Wkh,
           __half* __restrict__ Wvh, __half* __restrict__ Woh)
{
    const int z = blockIdx.z;
    const float* s = z == 0 ? Wq  : (z == 1 ? Wk  : (z == 2 ? Wv  : Wo));
    __half*      d = z == 0 ? Wqh : (z == 1 ? Wkh : (z == 2 ? Wvh : Woh));
    int i = blockIdx.x * 256 + threadIdx.x;
    float4 f = ((const float4*)s)[i];
    ((uint2*)d)[i] = make_uint2(pack_f16x2(f.x, f.y), pack_f16x2(f.z, f.w));
}

// ---------------------------------------------------------------------------
// pure-fp16 GEMM, cp.async double-buffered. C = X @ W (+bias) [*scale].
// Block 128x128, BK=32, 8 warps (4m x 2n), warp tile 32x64.
// MODE 0: __half out, head-split layout, scale applied.
// MODE 1: float out, row-major.
// ---------------------------------------------------------------------------
#define ASTR 40
#define BSTR 136
#define A_BYTES (128 * ASTR * 2)
#define B_BYTES (32 * BSTR * 2)
#define STAGE_BYTES (A_BYTES + B_BYTES)

template <int MODE>
__device__ __forceinline__ void gemm_f16_body(
    const __half* __restrict__ X, const __half* __restrict__ W,
    const float* __restrict__ bias, void* outp, float scale)
{
    __shared__ __align__(16) char sh[2 * STAGE_BYTES];

    const int tid  = threadIdx.x;
    const int wid  = tid >> 5;
    const int lane = tid & 31;
    const int g    = lane >> 2;
    const int tig  = lane & 3;
    const int wm   = (wid & 3) << 5;
    const int wn   = (wid >> 2) << 6;
    const int lrow = (lane & 7) + ((lane >> 3) & 1) * 8;
    const int lcol = (lane >> 4) << 3;

    const int m0 = blockIdx.y << 7;
    const int n0 = blockIdx.x << 7;

    const unsigned sh_b = (unsigned)__cvta_generic_to_shared(sh);

    float c[2][8][4];
#pragma unroll
    for (int mt = 0; mt < 2; mt++)
#pragma unroll
        for (int nt = 0; nt < 8; nt++)
#pragma unroll
            for (int j = 0; j < 4; j++) c[mt][nt][j] = 0.f;

    auto issue = [&](int k0, int s) {
        unsigned as = sh_b + s * STAGE_BYTES;
        unsigned bs = as + A_BYTES;
#pragma unroll
        for (int p = 0; p < 2; p++) {
            int i = tid + (p << 8);
            int r = i >> 2, cc = (i & 3) << 3;
            cp16(as + (r * ASTR + cc) * 2, X + (size_t)(m0 + r) * DMc + k0 + cc);
        }
#pragma unroll
        for (int p = 0; p < 2; p++) {
            int i = tid + (p << 8);
            int r = i >> 4, cc = (i & 15) << 3;
            cp16(bs + (r * BSTR + cc) * 2, W + (size_t)(k0 + r) * DMc + n0 + cc);
        }
        cp_commit();
    };

    issue(0, 0);
    int buf = 0;
    for (int kc = 0; kc < 16; kc++) {
        if (kc < 15) { issue((kc + 1) << 5, buf ^ 1); cp_wait<1>(); }
        else         { cp_wait<0>(); }
        __syncthreads();

        const unsigned as_b = sh_b + buf * STAGE_BYTES;
        const unsigned bs_b = as_b + A_BYTES;
#pragma unroll
        for (int ks = 0; ks < 2; ks++) {
            const int kb = ks << 4;
            unsigned a[2][4];
#pragma unroll
            for (int mt = 0; mt < 2; mt++) {
                unsigned addr = as_b +
                    (((wm + (mt << 4) + lrow) * ASTR) + kb + lcol) * 2;
                ldsm_x4(a[mt][0], a[mt][1], a[mt][2], a[mt][3], addr);
            }
#pragma unroll
            for (int np = 0; np < 4; np++) {
                unsigned addr = bs_b +
                    (((kb + lrow) * BSTR) + wn + (np << 4) + lcol) * 2;
                unsigned r0, r1, r2, r3;
                ldsm_x4_t(r0, r1, r2, r3, addr);
                mma_f16(c[0][2 * np],     a[0][0], a[0][1], a[0][2], a[0][3], r0, r1);
                mma_f16(c[0][2 * np + 1], a[0][0], a[0][1], a[0][2], a[0][3], r2, r3);
                mma_f16(c[1][2 * np],     a[1][0], a[1][1], a[1][2], a[1][3], r0, r1);
                mma_f16(c[1][2 * np + 1], a[1][0], a[1][1], a[1][2], a[1][3], r2, r3);
            }
        }
        __syncthreads();
        buf ^= 1;
    }

    const int b_ = m0 >> 12;
#pragma unroll
    for (int mt = 0; mt < 2; mt++) {
        int m  = m0 + wm + (mt << 4) + g;
        int s_ = m & (Sc - 1);
#pragma unroll
        for (int nt = 0; nt < 8; nt++) {
            int n = n0 + wn + (nt << 3) + (tig << 1);
            float bx = bias[n], by = bias[n + 1];
            if (MODE == 0) {
                __half* out = (__half*)outp;
                int h = n >> 6;
                int d = n & 63;
                unsigned u0 = pack_f16x2((c[mt][nt][0] + bx) * scale,
                                         (c[mt][nt][1] + by) * scale);
                unsigned u1 = pack_f16x2((c[mt][nt][2] + bx) * scale,
                                         (c[mt][nt][3] + by) * scale);
                __half* base = out + ((size_t)(b_ * Hc + h) * Sc) * Dc + d;
                *(unsigned*)(base + (size_t)s_ * Dc)       = u0;
                *(unsigned*)(base + (size_t)(s_ + 8) * Dc) = u1;
            } else {
                float* out = (float*)outp;
                *(float2*)(out + (size_t)m * DMc + n) =
                    make_float2(c[mt][nt][0] + bx, c[mt][nt][1] + by);
                *(float2*)(out + (size_t)(m + 8) * DMc + n) =
                    make_float2(c[mt][nt][2] + bx, c[mt][nt][3] + by);
            }
        }
    }
}

__global__ __launch_bounds__(256, 2)
void gemm_qkv(const __half* __restrict__ qh, const __half* __restrict__ kh,
              const __half* __restrict__ vh,
              const __half* __restrict__ Wqh, const __half* __restrict__ Wkh,
              const __half* __restrict__ Wvh,
              const float* __restrict__ bq, const float* __restrict__ bk,
              const float* __restrict__ bv,
              __half* __restrict__ Qp, __half* __restrict__ Kp,
              __half* __restrict__ Vp)
{
    const int z = blockIdx.z;
    const __half* X    = z == 0 ? qh  : (z == 1 ? kh  : vh);
    const __half* W    = z == 0 ? Wqh : (z == 1 ? Wkh : Wvh);
    const float*  bias = z == 0 ? bq  : (z == 1 ? bk  : bv);
    __half*       out  = z == 0 ? Qp  : (z == 1 ? Kp  : Vp);
    gemm_f16_body<0>(X, W, bias, out, z == 0 ? SCL : 1.0f);
}

__global__ __launch_bounds__(256, 2)
void gemm_out(const __half* __restrict__ X, const __half* __restrict__ W,
              const float* __restrict__ bias, float* __restrict__ out)
{
    gemm_f16_body<1>(X, W, bias, out, 1.0f);
}

// ---------------------------------------------------------------------------
// Flash attention, fp16 mma + ldmatrix, cp.async double-buffered K/V.
// Block: 128 threads (4 warps), BQ=128 (32 rows/warp), BK=64, D=64.
// smem halves: Qs[128][72] | Ks[2][64][72] | Vs[2][64][72] | mk[2][64] float
// l carried as a 9th output n-tile (ones-column mma); P via ex2.approx.f16x2.
// ---------------------------------------------------------------------------
#define HSTR 72
#define QS_HALVES (128 * HSTR)
#define KV_STAGE_HALVES (64 * HSTR)
#define KS_HOFF QS_HALVES
#define VS_HOFF (QS_HALVES + 2 * KV_STAGE_HALVES)
#define MK_BYTE_OFF ((QS_HALVES + 4 * KV_STAGE_HALVES) * 2)
#define ATTN_SMEM_BYTES (MK_BYTE_OFF + 2 * 64 * 4)

#define ONES16X2 0x3C003C00u

__global__ __launch_bounds__(128, 2)
void attn_f16(const __half* __restrict__ Qp, const __half* __restrict__ Kp,
              const __half* __restrict__ Vp, const float* __restrict__ mask,
              __half* __restrict__ Ao)
{
    extern __shared__ __align__(16) char smc[];
    __half* Qs = (__half*)smc;
    float*  mk = (float*)(smc + MK_BYTE_OFF);

    const unsigned qs_b = (unsigned)__cvta_generic_to_shared(smc);
    const unsigned ks_b = qs_b + KS_HOFF * 2;
    const unsigned vs_b = qs_b + VS_HOFF * 2;
    const unsigned mk_b = qs_b + MK_BYTE_OFF;

    const int tid  = threadIdx.x;
    const int wid  = tid >> 5;
    const int lane = tid & 31;
    const int g    = lane >> 2;
    const int tig  = lane & 3;
    const int wm   = wid << 5;
    const int lrow = (lane & 7) + ((lane >> 3) & 1) * 8;
    const int lcol = (lane >> 4) << 3;

    const int bh = blockIdx.y;
    const int b  = bh >> 3;
    const int h  = bh & 7;
    const int q0 = blockIdx.x << 7;

    const __half* Qb = Qp + ((size_t)bh * Sc + q0) * Dc;
    const __half* Kb = Kp + (size_t)bh * Sc * Dc;
    const __half* Vb = Vp + (size_t)bh * Sc * Dc;
    const float*  mb = mask + (size_t)b * Sc;

    // stage issuer: K/V tile t (64 rows) + mask slice into stage s
    auto issue = [&](int t, int s) {
        const __half* Kt = Kb + (size_t)(t << 6) * Dc;
        const __half* Vt = Vb + (size_t)(t << 6) * Dc;
        unsigned ks = ks_b + s * KV_STAGE_HALVES * 2;
        unsigned vs = vs_b + s * KV_STAGE_HALVES * 2;
#pragma unroll
        for (int p = 0; p < 4; p++) {
            int i = tid + (p << 7);
            int r = i >> 3, cc = (i & 7) << 3;
            cp16(ks + (r * HSTR + cc) * 2, Kt + r * Dc + cc);
            cp16(vs + (r * HSTR + cc) * 2, Vt + r * Dc + cc);
        }
        if (tid < 16) cp16(mk_b + s * 256 + tid * 16, mb + (t << 6) + tid * 4);
        cp_commit();
    };

    issue(0, 0);

    // Q tile copy (fp16, already scaled by gemm)
#pragma unroll
    for (int p = 0; p < 8; p++) {
        int i = tid + (p << 7);
        int r = i >> 3, cc = (i & 7) << 3;
        *(uint4*)&Qs[r * HSTR + cc] = *(const uint4*)(Qb + r * Dc + cc);
    }

    float m_i[4] = {-INFINITY, -INFINITY, -INFINITY, -INFINITY};
    // o[mt][8] is the ones-column accumulator = running row sum l
    float o[2][9][4];
#pragma unroll
    for (int mt = 0; mt < 2; mt++)
#pragma unroll
        for (int nt = 0; nt < 9; nt++)
#pragma unroll
            for (int j = 0; j < 4; j++) o[mt][nt][j] = 0.f;

    const int NT = Sc / 64;
    for (int t = 0; t < NT; t++) {
        const int s = t & 1;
        if (t < NT - 1) { issue(t + 1, s ^ 1); cp_wait<1>(); }
        else            { cp_wait<0>(); }
        __syncthreads();

        const unsigned ks_s = ks_b + s * KV_STAGE_HALVES * 2;
        const unsigned vs_s = vs_b + s * KV_STAGE_HALVES * 2;
        const float*   mks  = mk + s * 64;

        // ---- S = Q @ K^T ----
        float c[2][8][4];
#pragma unroll
        for (int mt = 0; mt < 2; mt++)
#pragma unroll
            for (int nt = 0; nt < 8; nt++)
#pragma unroll
                for (int j = 0; j < 4; j++) c[mt][nt][j] = 0.f;

#pragma unroll
        for (int kb4 = 0; kb4 < 4; kb4++) {
            const int kb = kb4 << 4;
            unsigned a[2][4];
#pragma unroll
            for (int mt = 0; mt < 2; mt++) {
                unsigned addr = qs_b +
                    (((wm + (mt << 4) + lrow) * HSTR) + kb + lcol) * 2;
                ldsm_x4(a[mt][0], a[mt][1], a[mt][2], a[mt][3], addr);
            }
#pragma unroll
            for (int np = 0; np < 4; np++) {
                unsigned addr = ks_s +
                    ((((np << 4) + lrow) * HSTR) + kb + lcol) * 2;
                unsigned b0e, b0o, b1e, b1o;
                ldsm_x4(b0e, b0o, b1e, b1o, addr);
                mma_f16(c[0][2 * np],     a[0][0], a[0][1], a[0][2], a[0][3], b0e, b1e);
                mma_f16(c[0][2 * np + 1], a[0][0], a[0][1], a[0][2], a[0][3], b0o, b1o);
                mma_f16(c[1][2 * np],     a[1][0], a[1][1], a[1][2], a[1][3], b0e, b1e);
                mma_f16(c[1][2 * np + 1], a[1][0], a[1][1], a[1][2], a[1][3], b0o, b1o);
            }
        }

        // ---- mask + online softmax (log2 domain, fp16x2 exp) ----
        unsigned pu[2][8][2];
#pragma unroll
        for (int mt = 0; mt < 2; mt++) {
            float vmax0 = -INFINITY, vmax1 = -INFINITY;
#pragma unroll
            for (int nt = 0; nt < 8; nt++) {
                float2 mv = *(const float2*)&mks[(nt << 3) + (tig << 1)];
                c[mt][nt][0] = fmaf(mv.x, MSK, c[mt][nt][0]);
                c[mt][nt][1] = fmaf(mv.y, MSK, c[mt][nt][1]);
                c[mt][nt][2] = fmaf(mv.x, MSK, c[mt][nt][2]);
                c[mt][nt][3] = fmaf(mv.y, MSK, c[mt][nt][3]);
                vmax0 = fmaxf(vmax0, fmaxf(c[mt][nt][0], c[mt][nt][1]));
                vmax1 = fmaxf(vmax1, fmaxf(c[mt][nt][2], c[mt][nt][3]));
            }
            vmax0 = fmaxf(vmax0, __shfl_xor_sync(0xffffffffu, vmax0, 1));
            vmax0 = fmaxf(vmax0, __shfl_xor_sync(0xffffffffu, vmax0, 2));
            vmax1 = fmaxf(vmax1, __shfl_xor_sync(0xffffffffu, vmax1, 1));
            vmax1 = fmaxf(vmax1, __shfl_xor_sync(0xffffffffu, vmax1, 2));

            float mn0 = fmaxf(m_i[mt * 2 + 0], vmax0);
            float mn1 = fmaxf(m_i[mt * 2 + 1], vmax1);
            float al0 = ex2(m_i[mt * 2 + 0] - mn0);
            float al1 = ex2(m_i[mt * 2 + 1] - mn1);
            m_i[mt * 2 + 0] = mn0;
            m_i[mt * 2 + 1] = mn1;

            // pack (s - mn) pairs and exponentiate in f16x2 -> P fragments
#pragma unroll
            for (int nt = 0; nt < 8; nt++) {
                pu[mt][nt][0] = ex2_f16x2(
                    pack_f16x2(c[mt][nt][0] - mn0, c[mt][nt][1] - mn0));
                pu[mt][nt][1] = ex2_f16x2(
                    pack_f16x2(c[mt][nt][2] - mn1, c[mt][nt][3] - mn1));
            }
            // rescale O and the l-column
#pragma unroll
            for (int nt = 0; nt < 9; nt++) {
                o[mt][nt][0] *= al0; o[mt][nt][1] *= al0;
                o[mt][nt][2] *= al1; o[mt][nt][3] *= al1;
            }
        }

        // ---- O += P @ V ;  l-column += P @ ones ----
#pragma unroll
        for (int kb4 = 0; kb4 < 4; kb4++) {
            unsigned pa[2][4];
#pragma unroll
            for (int mt = 0; mt < 2; mt++) {
                pa[mt][0] = pu[mt][2 * kb4][0];
                pa[mt][1] = pu[mt][2 * kb4][1];
                pa[mt][2] = pu[mt][2 * kb4 + 1][0];
                pa[mt][3] = pu[mt][2 * kb4 + 1][1];
            }
#pragma unroll
            for (int dp = 0; dp < 4; dp++) {
                unsigned addr = vs_s +
                    ((((kb4 << 4) + lrow) * HSTR) + (dp << 4) + lcol) * 2;
                unsigned r0, r1, r2, r3;
                ldsm_x4_t(r0, r1, r2, r3, addr);
                mma_f16(o[0][2 * dp],     pa[0][0], pa[0][1], pa[0][2], pa[0][3], r0, r1);
                mma_f16(o[0][2 * dp + 1], pa[0][0], pa[0][1], pa[0][2], pa[0][3], r2, r3);
                mma_f16(o[1][2 * dp],     pa[1][0], pa[1][1], pa[1][2], pa[1][3], r0, r1);
                mma_f16(o[1][2 * dp + 1], pa[1][0], pa[1][1], pa[1][2], pa[1][3], r2, r3);
            }
            mma_f16(o[0][8], pa[0][0], pa[0][1], pa[0][2], pa[0][3],
                    ONES16X2, ONES16X2);
            mma_f16(o[1][8], pa[1][0], pa[1][1], pa[1][2], pa[1][3],
                    ONES16X2, ONES16X2);
        }
        __syncthreads();
    }

    // ---- epilogue: normalize by l (ones-column), write fp16 Ao ----
    __half* AoB = Ao + ((size_t)b * Sc) * DMc + h * Dc;
#pragma unroll
    for (int mt = 0; mt < 2; mt++) {
        float inv0 = 1.f / o[mt][8][0];
        float inv1 = 1.f / o[mt][8][2];
        int r0 = q0 + wm + (mt << 4) + g;
#pragma unroll
        for (int nt = 0; nt < 8; nt++) {
            int d = (nt << 3) + (tig << 1);
            *(unsigned*)(AoB + (size_t)r0 * DMc + d) =
                pack_f16x2(o[mt][nt][0] * inv0, o[mt][nt][1] * inv0);
            *(unsigned*)(AoB + (size_t)(r0 + 8) * DMc + d) =
                pack_f16x2(o[mt][nt][2] * inv1, o[mt][nt][3] * inv1);
        }
    }
}

// ---------------------------------------------------------------------------
extern "C" void kernel_launch(void* const* d_in, const int* in_sizes, int n_in,
                              void* d_out, int out_size)
{
    const float* q    = (const float*)d_in[0];
    const float* k    = (const float*)d_in[1];
    const float* v    = (const float*)d_in[2];
    const float* mask = (const float*)d_in[3];
    const float* Wq   = (const float*)d_in[4];
    const float* bq   = (const float*)d_in[5];
    const float* Wk   = (const float*)d_in[6];
    const float* bk   = (const float*)d_in[7];
    const float* Wv   = (const float*)d_in[8];
    const float* bv   = (const float*)d_in[9];
    const float* Wo   = (const float*)d_in[10];
    const float* bo   = (const float*)d_in[11];
    float* out = (float*)d_out;

    __half *qh, *kh, *vh, *Wqh, *Wkh, *Wvh, *Woh, *Qp, *Kp, *Vp, *Ao;
    cudaGetSymbolAddress((void**)&qh,  g_qh);
    cudaGetSymbolAddress((void**)&kh,  g_kh);
    cudaGetSymbolAddress((void**)&vh,  g_vh);
    cudaGetSymbolAddress((void**)&Wqh, g_Wqh);
    cudaGetSymbolAddress((void**)&Wkh, g_Wkh);
    cudaGetSymbolAddress((void**)&Wvh, g_Wvh);
    cudaGetSymbolAddress((void**)&Woh, g_Woh);
    cudaGetSymbolAddress((void**)&Qp,  g_Qp);
    cudaGetSymbolAddress((void**)&Kp,  g_Kp);
    cudaGetSymbolAddress((void**)&Vp,  g_Vp);
    cudaGetSymbolAddress((void**)&Ao,  g_Ao);

    cudaFuncSetAttribute(attn_f16, cudaFuncAttributeMaxDynamicSharedMemorySize,
                         ATTN_SMEM_BYTES);

    dim3 gin(Mc * DMc / 4 / 256, 1, 3);     // (4096,1,3)
    cvt_in<<<gin, 256>>>(q, k, v, qh, kh, vh);
    dim3 gw(DMc * DMc / 4 / 256, 1, 4);     // (256,1,4)
    cvt_w<<<gw, 256>>>(Wq, Wk, Wv, Wo, Wqh, Wkh, Wvh, Woh);

    dim3 gqkv(DMc / 128, Mc / 128, 3);      // (4, 64, 3)
    gemm_qkv<<<gqkv, 256>>>(qh, kh, vh, Wqh, Wkh, Wvh, bq, bk, bv, Qp, Kp, Vp);

    dim3 ga(Sc / 128, Bc * Hc);             // (32, 16)
    attn_f16<<<ga, 128, ATTN_SMEM_BYTES>>>(Qp, Kp, Vp, mask, Ao);

    dim3 gg(DMc / 128, Mc / 128);           // (4, 64)
    gemm_out<<<gg, 256>>>(Ao, Woh, bo, out);
}